// round 1
// baseline (speedup 1.0000x reference)
#include <cuda_runtime.h>
#include <math.h>

#define Bq 2
#define Mq 2048
#define Nq 1024
#define Hh 16
#define Dd 64
#define N3 3072   // 3*Nq
#define MB (Bq*Mq)  // 4096 total rows

// Scratch (device globals: allowed; no cudaMalloc permitted)
__device__ float g_qkv[(size_t)MB * N3];   // [B*M, 3N]
__device__ float g_ctx[(size_t)MB * Nq];   // [B*M, N]

// ---------------------------------------------------------------------------
// Tiled fp32 GEMM: C[M,N] = A[M,K] @ W[K,N] + bias[N]
// BM=BN=64, BK=16, 256 threads, 4x4 micro-tile per thread.
// ---------------------------------------------------------------------------
__global__ void gemm_bias_kernel(const float* __restrict__ A,
                                 const float* __restrict__ W,
                                 const float* __restrict__ bias,
                                 float* __restrict__ C,
                                 int M, int K, int N) {
    const int BM = 64, BN = 64, BK = 16;
    __shared__ float As[BK][BM];   // A transposed tile
    __shared__ float Bs[BK][BN];

    int tid = threadIdx.x;          // 0..255
    int tx = tid & 15;              // N direction
    int ty = tid >> 4;              // M direction
    int bm0 = blockIdx.y * BM;
    int bn0 = blockIdx.x * BN;

    float acc[4][4] = {};

    for (int k0 = 0; k0 < K; k0 += BK) {
        // Load A tile (BM x BK), store transposed
        #pragma unroll
        for (int l = tid; l < BM * BK; l += 256) {
            int m = l >> 4;          // /BK
            int k = l & 15;          // %BK
            As[k][m] = A[(size_t)(bm0 + m) * K + k0 + k];
        }
        // Load B tile (BK x BN)
        #pragma unroll
        for (int l = tid; l < BK * BN; l += 256) {
            int k = l >> 6;          // /BN
            int n = l & 63;          // %BN
            Bs[k][n] = W[(size_t)(k0 + k) * N + bn0 + n];
        }
        __syncthreads();

        #pragma unroll
        for (int kk = 0; kk < BK; kk++) {
            float a[4], b[4];
            #pragma unroll
            for (int i = 0; i < 4; i++) a[i] = As[kk][ty * 4 + i];
            #pragma unroll
            for (int j = 0; j < 4; j++) b[j] = Bs[kk][tx * 4 + j];
            #pragma unroll
            for (int i = 0; i < 4; i++)
                #pragma unroll
                for (int j = 0; j < 4; j++)
                    acc[i][j] += a[i] * b[j];
        }
        __syncthreads();
    }

    #pragma unroll
    for (int i = 0; i < 4; i++) {
        int m = bm0 + ty * 4 + i;
        #pragma unroll
        for (int j = 0; j < 4; j++) {
            int n = bn0 + tx * 4 + j;
            C[(size_t)m * N + n] = acc[i][j] + bias[n];
        }
    }
}

// ---------------------------------------------------------------------------
// Causal flash attention, fp32.
// One thread = one query row. BQ=128 rows per block, K/V tiles of KB=16.
// Masked (future) keys are skipped: reference's -10000 bias underflows
// exp() to exactly 0.0f in fp32, so skipping is numerically identical.
// ---------------------------------------------------------------------------
#define BQ 128
#define KB 16

__global__ void attn_kernel() {
    int bh = blockIdx.y;
    int b = bh / Hh;
    int h = bh % Hh;
    int q0 = blockIdx.x * BQ;
    int tid = threadIdx.x;           // 0..127

    __shared__ float Qs[BQ][Dd + 1]; // +1 pad: conflict-free per-row reads
    __shared__ float Ks[KB][Dd];
    __shared__ float Vs[KB][Dd];

    const float scale = 0.125f;      // 1/sqrt(64)

    const float* qbase = g_qkv + ((size_t)(b * Mq + q0)) * N3 + h * Dd;
    const float* kbase = g_qkv + ((size_t)(b * Mq)) * N3 + Nq + h * Dd;
    const float* vbase = g_qkv + ((size_t)(b * Mq)) * N3 + 2 * Nq + h * Dd;

    // cooperative Q tile load
    #pragma unroll
    for (int l = tid; l < BQ * Dd; l += BQ) {
        int r = l >> 6;
        int dd = l & 63;
        Qs[r][dd] = qbase[(size_t)r * N3 + dd];
    }

    int qi = q0 + tid;
    float mrun = -1e30f, lsum = 0.0f;
    float O[Dd];
    #pragma unroll
    for (int dd = 0; dd < Dd; dd++) O[dd] = 0.0f;

    int nkb = (q0 + BQ + KB - 1) / KB;  // blocks up to causal limit of this tile

    for (int kb = 0; kb < nkb; kb++) {
        int kstart = kb * KB;
        __syncthreads();   // protect Ks/Vs from previous iter (also covers Q load)
        #pragma unroll
        for (int l = tid; l < KB * Dd; l += BQ) {
            int r = l >> 6;
            int dd = l & 63;
            Ks[r][dd] = kbase[(size_t)(kstart + r) * N3 + dd];
            Vs[r][dd] = vbase[(size_t)(kstart + r) * N3 + dd];
        }
        __syncthreads();

        // scores for this thread's query row
        float s[KB];
        #pragma unroll
        for (int j = 0; j < KB; j++) s[j] = 0.0f;
        #pragma unroll 8
        for (int dd = 0; dd < Dd; dd++) {
            float qv = Qs[tid][dd];
            #pragma unroll
            for (int j = 0; j < KB; j++) s[j] += qv * Ks[j][dd];
        }

        // online softmax update (causal mask via skip)
        float bmax = mrun;
        #pragma unroll
        for (int j = 0; j < KB; j++)
            if (kstart + j <= qi) bmax = fmaxf(bmax, s[j] * scale);

        float corr = __expf(mrun - bmax);
        mrun = bmax;

        float e[KB];
        float esum = 0.0f;
        #pragma unroll
        for (int j = 0; j < KB; j++) {
            e[j] = (kstart + j <= qi) ? __expf(s[j] * scale - mrun) : 0.0f;
            esum += e[j];
        }
        lsum = lsum * corr + esum;

        #pragma unroll
        for (int dd = 0; dd < Dd; dd++) O[dd] *= corr;
        #pragma unroll
        for (int j = 0; j < KB; j++) {
            float p = e[j];
            #pragma unroll
            for (int dd = 0; dd < Dd; dd++) O[dd] += p * Vs[j][dd];
        }
    }

    float inv = 1.0f / lsum;
    float* obase = g_ctx + ((size_t)(b * Mq + qi)) * Nq + h * Dd;
    #pragma unroll
    for (int dd = 0; dd < Dd; dd++) obase[dd] = O[dd] * inv;
}

// ---------------------------------------------------------------------------
extern "C" void kernel_launch(void* const* d_in, const int* in_sizes, int n_in,
                              void* d_out, int out_size) {
    const float* x      = (const float*)d_in[0];   // [B,M,N]
    const float* w_attn = (const float*)d_in[1];   // [N,3N]
    const float* w_proj = (const float*)d_in[2];   // [N,N]
    const float* b_attn = (const float*)d_in[3];   // [3N]
    const float* b_proj = (const float*)d_in[4];   // [N]
    float* out = (float*)d_out;                    // [B,M,N]

    float* qkv = nullptr;
    float* ctx = nullptr;
    cudaGetSymbolAddress((void**)&qkv, g_qkv);
    cudaGetSymbolAddress((void**)&ctx, g_ctx);

    // 1) QKV projection: [4096,1024] @ [1024,3072]
    {
        dim3 grid(N3 / 64, MB / 64);
        gemm_bias_kernel<<<grid, 256>>>(x, w_attn, b_attn, qkv, MB, Nq, N3);
    }
    // 2) causal attention -> ctx
    {
        dim3 grid(Mq / BQ, Bq * Hh);
        attn_kernel<<<grid, BQ>>>();
    }
    // 3) output projection: [4096,1024] @ [1024,1024]
    {
        dim3 grid(Nq / 64, MB / 64);
        gemm_bias_kernel<<<grid, 256>>>(ctx, w_proj, b_proj, out, MB, Nq, Nq);
    }
}

// round 2
// speedup vs baseline: 1.0060x; 1.0060x over previous
#include <cuda_runtime.h>
#include <math.h>

#define Bq 2
#define Mq 2048
#define Nq 1024
#define Hh 16
#define Dd 64
#define N3 3072   // 3*Nq
#define MB (Bq*Mq)  // 4096 total rows

// Scratch (device globals: allowed; no cudaMalloc permitted)
__device__ float g_qkv[(size_t)MB * N3];   // [B*M, 3N]
__device__ float g_ctx[(size_t)MB * Nq];   // [B*M, N]

// ---------------------------------------------------------------------------
// Tiled fp32 GEMM: C[M,N] = A[M,K] @ W[K,N] + bias[N]
// BM=BN=64, BK=16, 256 threads, 4x4 micro-tile per thread.
// ---------------------------------------------------------------------------
__global__ void gemm_bias_kernel(const float* __restrict__ A,
                                 const float* __restrict__ W,
                                 const float* __restrict__ bias,
                                 float* __restrict__ C,
                                 int M, int K, int N) {
    const int BM = 64, BN = 64, BK = 16;
    __shared__ float As[BK][BM];   // A transposed tile
    __shared__ float Bs[BK][BN];

    int tid = threadIdx.x;          // 0..255
    int tx = tid & 15;              // N direction
    int ty = tid >> 4;              // M direction
    int bm0 = blockIdx.y * BM;
    int bn0 = blockIdx.x * BN;

    float acc[4][4] = {};

    for (int k0 = 0; k0 < K; k0 += BK) {
        // Load A tile (BM x BK), store transposed
        #pragma unroll
        for (int l = tid; l < BM * BK; l += 256) {
            int m = l >> 4;          // /BK
            int k = l & 15;          // %BK
            As[k][m] = A[(size_t)(bm0 + m) * K + k0 + k];
        }
        // Load B tile (BK x BN)
        #pragma unroll
        for (int l = tid; l < BK * BN; l += 256) {
            int k = l >> 6;          // /BN
            int n = l & 63;          // %BN
            Bs[k][n] = W[(size_t)(k0 + k) * N + bn0 + n];
        }
        __syncthreads();

        #pragma unroll
        for (int kk = 0; kk < BK; kk++) {
            float a[4], b[4];
            #pragma unroll
            for (int i = 0; i < 4; i++) a[i] = As[kk][ty * 4 + i];
            #pragma unroll
            for (int j = 0; j < 4; j++) b[j] = Bs[kk][tx * 4 + j];
            #pragma unroll
            for (int i = 0; i < 4; i++)
                #pragma unroll
                for (int j = 0; j < 4; j++)
                    acc[i][j] += a[i] * b[j];
        }
        __syncthreads();
    }

    #pragma unroll
    for (int i = 0; i < 4; i++) {
        int m = bm0 + ty * 4 + i;
        #pragma unroll
        for (int j = 0; j < 4; j++) {
            int n = bn0 + tx * 4 + j;
            C[(size_t)m * N + n] = acc[i][j] + bias[n];
        }
    }
}

// ---------------------------------------------------------------------------
// Causal flash attention, fp32.
// One thread = one query row. BQ=128 rows per block, K/V tiles of KB=16.
// Masked (future) keys are skipped: reference's -10000 bias underflows
// exp() to exactly 0.0f in fp32, so skipping is numerically identical.
// ---------------------------------------------------------------------------
#define BQ 128
#define KB 16

__global__ void attn_kernel() {
    int bh = blockIdx.y;
    int b = bh / Hh;
    int h = bh % Hh;
    int q0 = blockIdx.x * BQ;
    int tid = threadIdx.x;           // 0..127

    __shared__ float Qs[BQ][Dd + 1]; // +1 pad: conflict-free per-row reads
    __shared__ float Ks[KB][Dd];
    __shared__ float Vs[KB][Dd];

    const float scale = 0.125f;      // 1/sqrt(64)

    const float* qbase = g_qkv + ((size_t)(b * Mq + q0)) * N3 + h * Dd;
    const float* kbase = g_qkv + ((size_t)(b * Mq)) * N3 + Nq + h * Dd;
    const float* vbase = g_qkv + ((size_t)(b * Mq)) * N3 + 2 * Nq + h * Dd;

    // cooperative Q tile load
    #pragma unroll
    for (int l = tid; l < BQ * Dd; l += BQ) {
        int r = l >> 6;
        int dd = l & 63;
        Qs[r][dd] = qbase[(size_t)r * N3 + dd];
    }

    int qi = q0 + tid;
    float mrun = -1e30f, lsum = 0.0f;
    float O[Dd];
    #pragma unroll
    for (int dd = 0; dd < Dd; dd++) O[dd] = 0.0f;

    int nkb = (q0 + BQ + KB - 1) / KB;  // blocks up to causal limit of this tile

    for (int kb = 0; kb < nkb; kb++) {
        int kstart = kb * KB;
        __syncthreads();   // protect Ks/Vs from previous iter (also covers Q load)
        #pragma unroll
        for (int l = tid; l < KB * Dd; l += BQ) {
            int r = l >> 6;
            int dd = l & 63;
            Ks[r][dd] = kbase[(size_t)(kstart + r) * N3 + dd];
            Vs[r][dd] = vbase[(size_t)(kstart + r) * N3 + dd];
        }
        __syncthreads();

        // scores for this thread's query row
        float s[KB];
        #pragma unroll
        for (int j = 0; j < KB; j++) s[j] = 0.0f;
        #pragma unroll 8
        for (int dd = 0; dd < Dd; dd++) {
            float qv = Qs[tid][dd];
            #pragma unroll
            for (int j = 0; j < KB; j++) s[j] += qv * Ks[j][dd];
        }

        // online softmax update (causal mask via skip)
        float bmax = mrun;
        #pragma unroll
        for (int j = 0; j < KB; j++)
            if (kstart + j <= qi) bmax = fmaxf(bmax, s[j] * scale);

        float corr = __expf(mrun - bmax);
        mrun = bmax;

        float e[KB];
        float esum = 0.0f;
        #pragma unroll
        for (int j = 0; j < KB; j++) {
            e[j] = (kstart + j <= qi) ? __expf(s[j] * scale - mrun) : 0.0f;
            esum += e[j];
        }
        lsum = lsum * corr + esum;

        #pragma unroll
        for (int dd = 0; dd < Dd; dd++) O[dd] *= corr;
        #pragma unroll
        for (int j = 0; j < KB; j++) {
            float p = e[j];
            #pragma unroll
            for (int dd = 0; dd < Dd; dd++) O[dd] += p * Vs[j][dd];
        }
    }

    float inv = 1.0f / lsum;
    float* obase = g_ctx + ((size_t)(b * Mq + qi)) * Nq + h * Dd;
    #pragma unroll
    for (int dd = 0; dd < Dd; dd++) obase[dd] = O[dd] * inv;
}

// ---------------------------------------------------------------------------
extern "C" void kernel_launch(void* const* d_in, const int* in_sizes, int n_in,
                              void* d_out, int out_size) {
    const float* x      = (const float*)d_in[0];   // [B,M,N]
    const float* w_attn = (const float*)d_in[1];   // [N,3N]
    const float* w_proj = (const float*)d_in[2];   // [N,N]
    const float* b_attn = (const float*)d_in[3];   // [3N]
    const float* b_proj = (const float*)d_in[4];   // [N]
    float* out = (float*)d_out;                    // [B,M,N]

    float* qkv = nullptr;
    float* ctx = nullptr;
    cudaGetSymbolAddress((void**)&qkv, g_qkv);
    cudaGetSymbolAddress((void**)&ctx, g_ctx);

    // 1) QKV projection: [4096,1024] @ [1024,3072]
    {
        dim3 grid(N3 / 64, MB / 64);
        gemm_bias_kernel<<<grid, 256>>>(x, w_attn, b_attn, qkv, MB, Nq, N3);
    }
    // 2) causal attention -> ctx
    {
        dim3 grid(Mq / BQ, Bq * Hh);
        attn_kernel<<<grid, BQ>>>();
    }
    // 3) output projection: [4096,1024] @ [1024,1024]
    {
        dim3 grid(Nq / 64, MB / 64);
        gemm_bias_kernel<<<grid, 256>>>(ctx, w_proj, b_proj, out, MB, Nq, Nq);
    }
}

// round 3
// speedup vs baseline: 1.4608x; 1.4520x over previous
#include <cuda_runtime.h>
#include <math.h>

#define Bq 2
#define Mq 2048
#define Nq 1024
#define Hh 16
#define Dd 64
#define N3 3072
#define MB (Bq*Mq)

__device__ __align__(16) float g_qkv[(size_t)MB * N3];
__device__ __align__(16) float g_ctx[(size_t)MB * Nq];

// ---- f32x2 packed helpers (Blackwell packed fp32 pipe; PTX-only) ----------
__device__ __forceinline__ unsigned long long pack2(float lo, float hi) {
    unsigned long long r;
    asm("mov.b64 %0, {%1, %2};" : "=l"(r) : "f"(lo), "f"(hi));
    return r;
}
__device__ __forceinline__ unsigned long long bcast2(float v) {
    unsigned long long r;
    asm("mov.b64 %0, {%1, %1};" : "=l"(r) : "f"(v));
    return r;
}
__device__ __forceinline__ void fma2(unsigned long long& d,
                                     unsigned long long a,
                                     unsigned long long b) {
    asm("fma.rn.f32x2 %0, %1, %2, %0;" : "+l"(d) : "l"(a), "l"(b));
}
__device__ __forceinline__ void mul2(unsigned long long& d,
                                     unsigned long long a) {
    asm("mul.rn.f32x2 %0, %0, %1;" : "+l"(d) : "l"(a));
}
__device__ __forceinline__ float2 unpk(unsigned long long v) {
    float2 r;
    r.x = __uint_as_float((unsigned)(v & 0xffffffffull));
    r.y = __uint_as_float((unsigned)(v >> 32));
    return r;
}

// ---------------------------------------------------------------------------
// GEMM: C[M,N] = A[M,K] @ W[K,N] + bias. 128x128x16 tile, 8x8 micro,
// double-buffered smem, f32x2 packed accumulation.
// ---------------------------------------------------------------------------
#define GBM 128
#define GBN 128
#define GBK 16

__global__ __launch_bounds__(256, 2)
void gemm_bias_v2(const float* __restrict__ A, const float* __restrict__ W,
                  const float* __restrict__ bias, float* __restrict__ C,
                  int M, int K, int N) {
    __shared__ __align__(16) float As[2][GBK][GBM];
    __shared__ __align__(16) float Bs[2][GBK][GBN];

    int tid = threadIdx.x;
    int tx = tid & 15;        // N dir (8 cols each)
    int ty = tid >> 4;        // M dir (8 rows each)
    int bm0 = blockIdx.y * GBM;
    int bn0 = blockIdx.x * GBN;

    int a_c4 = (tid >> 6) * 4;   // 0,4,8,12  (k within tile)
    int a_r  = tid & 63;         // row 0..63 (+64 second)
    int b_r  = tid >> 4;         // 0..15     (k within tile)
    int b_c  = (tid & 15) * 4;   // 0..60     (+64 second)

    const float* A0 = A + (size_t)(bm0 + a_r) * K + a_c4;
    const float* A1 = A0 + (size_t)64 * K;
    const float* W0 = W + (size_t)b_r * N + bn0 + b_c;

    float4 pa0 = *(const float4*)A0;
    float4 pa1 = *(const float4*)A1;
    float4 pb0 = *(const float4*)W0;
    float4 pb1 = *(const float4*)(W0 + 64);

    As[0][a_c4+0][a_r]    = pa0.x; As[0][a_c4+1][a_r]    = pa0.y;
    As[0][a_c4+2][a_r]    = pa0.z; As[0][a_c4+3][a_r]    = pa0.w;
    As[0][a_c4+0][a_r+64] = pa1.x; As[0][a_c4+1][a_r+64] = pa1.y;
    As[0][a_c4+2][a_r+64] = pa1.z; As[0][a_c4+3][a_r+64] = pa1.w;
    *(float4*)&Bs[0][b_r][b_c]      = pb0;
    *(float4*)&Bs[0][b_r][b_c + 64] = pb1;
    __syncthreads();

    unsigned long long acc[8][4];
    #pragma unroll
    for (int i = 0; i < 8; i++)
        #pragma unroll
        for (int j = 0; j < 4; j++) acc[i][j] = 0ull;

    int ntiles = K / GBK;
    int buf = 0;
    for (int kt = 0; kt < ntiles; kt++) {
        if (kt + 1 < ntiles) {
            pa0 = *(const float4*)(A0 + (kt + 1) * GBK);
            pa1 = *(const float4*)(A1 + (kt + 1) * GBK);
            pb0 = *(const float4*)(W0 + (size_t)(kt + 1) * GBK * N);
            pb1 = *(const float4*)(W0 + (size_t)(kt + 1) * GBK * N + 64);
        }
        #pragma unroll
        for (int kk = 0; kk < GBK; kk++) {
            float4 av0 = *(const float4*)&As[buf][kk][ty * 8];
            float4 av1 = *(const float4*)&As[buf][kk][ty * 8 + 4];
            ulonglong2 bb0 = *(const ulonglong2*)&Bs[buf][kk][tx * 8];
            ulonglong2 bb1 = *(const ulonglong2*)&Bs[buf][kk][tx * 8 + 4];
            unsigned long long b2[4] = {bb0.x, bb0.y, bb1.x, bb1.y};
            float a[8] = {av0.x, av0.y, av0.z, av0.w, av1.x, av1.y, av1.z, av1.w};
            #pragma unroll
            for (int i = 0; i < 8; i++) {
                unsigned long long a2 = bcast2(a[i]);
                #pragma unroll
                for (int j = 0; j < 4; j++) fma2(acc[i][j], a2, b2[j]);
            }
        }
        int nb = buf ^ 1;
        if (kt + 1 < ntiles) {
            As[nb][a_c4+0][a_r]    = pa0.x; As[nb][a_c4+1][a_r]    = pa0.y;
            As[nb][a_c4+2][a_r]    = pa0.z; As[nb][a_c4+3][a_r]    = pa0.w;
            As[nb][a_c4+0][a_r+64] = pa1.x; As[nb][a_c4+1][a_r+64] = pa1.y;
            As[nb][a_c4+2][a_r+64] = pa1.z; As[nb][a_c4+3][a_r+64] = pa1.w;
            *(float4*)&Bs[nb][b_r][b_c]      = pb0;
            *(float4*)&Bs[nb][b_r][b_c + 64] = pb1;
        }
        __syncthreads();
        buf = nb;
    }

    float4 bia0 = *(const float4*)&bias[bn0 + tx * 8];
    float4 bia1 = *(const float4*)&bias[bn0 + tx * 8 + 4];
    #pragma unroll
    for (int i = 0; i < 8; i++) {
        int m = bm0 + ty * 8 + i;
        float2 t0 = unpk(acc[i][0]);
        float2 t1 = unpk(acc[i][1]);
        float2 t2 = unpk(acc[i][2]);
        float2 t3 = unpk(acc[i][3]);
        float4 o0 = {t0.x + bia0.x, t0.y + bia0.y, t1.x + bia0.z, t1.y + bia0.w};
        float4 o1 = {t2.x + bia1.x, t2.y + bia1.y, t3.x + bia1.z, t3.y + bia1.w};
        *(float4*)&C[(size_t)m * N + bn0 + tx * 8]     = o0;
        *(float4*)&C[(size_t)m * N + bn0 + tx * 8 + 4] = o1;
    }
}

// ---------------------------------------------------------------------------
// Causal flash attention, f32x2 packed, vectorized LDS.
// One thread = one query row. BQ=128, key tiles KB=16. Masked keys skipped
// (identical to reference: exp(-10000 offset) underflows to 0 in fp32).
// ---------------------------------------------------------------------------
#define BQ 128
#define KB 16

__global__ __launch_bounds__(BQ)
void attn_kernel() {
    int bh = blockIdx.y;
    int b = bh >> 4;
    int h = bh & 15;
    int q0 = blockIdx.x * BQ;
    int tid = threadIdx.x;

    __shared__ __align__(16) float Qs[BQ][Dd + 4];  // +4: conflict-free & 16B-aligned
    __shared__ __align__(16) float Ks[KB][Dd];
    __shared__ __align__(16) float Vs[KB][Dd];

    const float scale = 0.125f;

    const float* qbase = g_qkv + ((size_t)(b * Mq + q0)) * N3 + h * Dd;
    const float* kbase = g_qkv + ((size_t)(b * Mq)) * N3 + Nq + h * Dd;
    const float* vbase = g_qkv + ((size_t)(b * Mq)) * N3 + 2 * Nq + h * Dd;

    #pragma unroll
    for (int l = tid; l < BQ * 16; l += BQ) {
        int r = l >> 4;
        int c4 = (l & 15) * 4;
        *(float4*)&Qs[r][c4] = *(const float4*)&qbase[(size_t)r * N3 + c4];
    }

    int qi = q0 + tid;
    float mrun = -1e30f, lsum = 0.0f;
    unsigned long long O2[32];
    #pragma unroll
    for (int k = 0; k < 32; k++) O2[k] = 0ull;

    int nkb = (q0 + BQ) / KB;

    for (int kb = 0; kb < nkb; kb++) {
        int kstart = kb * KB;
        __syncthreads();
        {
            int r = tid >> 4;            // 0..7
            int c4 = (tid & 15) * 4;
            *(float4*)&Ks[r][c4]     = *(const float4*)&kbase[(size_t)(kstart + r) * N3 + c4];
            *(float4*)&Ks[r + 8][c4] = *(const float4*)&kbase[(size_t)(kstart + r + 8) * N3 + c4];
            *(float4*)&Vs[r][c4]     = *(const float4*)&vbase[(size_t)(kstart + r) * N3 + c4];
            *(float4*)&Vs[r + 8][c4] = *(const float4*)&vbase[(size_t)(kstart + r + 8) * N3 + c4];
        }
        __syncthreads();

        // --- QK^T for this thread's query row (packed over d) ---
        unsigned long long sacc[KB];
        #pragma unroll
        for (int j = 0; j < KB; j++) sacc[j] = 0ull;
        #pragma unroll 4
        for (int dd = 0; dd < Dd; dd += 4) {
            ulonglong2 q2 = *(const ulonglong2*)&Qs[tid][dd];
            #pragma unroll
            for (int j = 0; j < KB; j++) {
                ulonglong2 k2 = *(const ulonglong2*)&Ks[j][dd];
                fma2(sacc[j], q2.x, k2.x);
                fma2(sacc[j], q2.y, k2.y);
            }
        }
        float s[KB];
        #pragma unroll
        for (int j = 0; j < KB; j++) {
            float2 t = unpk(sacc[j]);
            s[j] = (t.x + t.y) * scale;
        }

        // --- online softmax (masked keys contribute exactly 0) ---
        float bmax = mrun;
        #pragma unroll
        for (int j = 0; j < KB; j++)
            if (kstart + j <= qi) bmax = fmaxf(bmax, s[j]);
        float corr = __expf(mrun - bmax);
        mrun = bmax;

        float e[KB];
        float esum = 0.0f;
        #pragma unroll
        for (int j = 0; j < KB; j++) {
            e[j] = (kstart + j <= qi) ? __expf(s[j] - mrun) : 0.0f;
            esum += e[j];
        }
        lsum = lsum * corr + esum;

        unsigned long long c2 = bcast2(corr);
        #pragma unroll
        for (int k = 0; k < 32; k++) mul2(O2[k], c2);

        // --- P @ V (packed over d) ---
        #pragma unroll 4
        for (int j = 0; j < KB; j++) {
            unsigned long long p2 = bcast2(e[j]);
            #pragma unroll
            for (int dp = 0; dp < 32; dp += 2) {
                ulonglong2 v2 = *(const ulonglong2*)&Vs[j][dp * 2];
                fma2(O2[dp],     p2, v2.x);
                fma2(O2[dp + 1], p2, v2.y);
            }
        }
    }

    float inv = 1.0f / lsum;
    float* obase = g_ctx + ((size_t)(b * Mq + qi)) * Nq + h * Dd;
    #pragma unroll
    for (int dp = 0; dp < 32; dp += 2) {
        float2 t0 = unpk(O2[dp]);
        float2 t1 = unpk(O2[dp + 1]);
        float4 o = {t0.x * inv, t0.y * inv, t1.x * inv, t1.y * inv};
        *(float4*)&obase[dp * 2] = o;
    }
}

// ---------------------------------------------------------------------------
extern "C" void kernel_launch(void* const* d_in, const int* in_sizes, int n_in,
                              void* d_out, int out_size) {
    const float* x      = (const float*)d_in[0];
    const float* w_attn = (const float*)d_in[1];
    const float* w_proj = (const float*)d_in[2];
    const float* b_attn = (const float*)d_in[3];
    const float* b_proj = (const float*)d_in[4];
    float* out = (float*)d_out;

    float* qkv = nullptr;
    float* ctx = nullptr;
    cudaGetSymbolAddress((void**)&qkv, g_qkv);
    cudaGetSymbolAddress((void**)&ctx, g_ctx);

    {   // QKV projection: [4096,1024] @ [1024,3072]
        dim3 grid(N3 / GBN, MB / GBM);
        gemm_bias_v2<<<grid, 256>>>(x, w_attn, b_attn, qkv, MB, Nq, N3);
    }
    {   // causal attention
        dim3 grid(Mq / BQ, Bq * Hh);
        attn_kernel<<<grid, BQ>>>();
    }
    {   // output projection: [4096,1024] @ [1024,1024]
        dim3 grid(Nq / GBN, MB / GBM);
        gemm_bias_v2<<<grid, 256>>>(ctx, w_proj, b_proj, out, MB, Nq, Nq);
    }
}

// round 5
// speedup vs baseline: 2.1252x; 1.4548x over previous
#include <cuda_runtime.h>
#include <cuda_bf16.h>
#include <cstdint>
#include <math.h>

#define Bq 2
#define Mq 2048
#define Nq 1024
#define Hh 16
#define Dd 64
#define N3 3072
#define MB (Bq*Mq)

// ---------------- scratch (device globals; no cudaMalloc allowed) ----------
__device__ __align__(16) float g_qkv[(size_t)MB * N3];          // fp32 QKV
__device__ __align__(16) __nv_bfloat16 g_xh[(size_t)MB * Nq];   // x split
__device__ __align__(16) __nv_bfloat16 g_xl[(size_t)MB * Nq];
__device__ __align__(16) __nv_bfloat16 g_wah[(size_t)N3 * Nq];  // w_attn^T split [n][k]
__device__ __align__(16) __nv_bfloat16 g_wal[(size_t)N3 * Nq];
__device__ __align__(16) __nv_bfloat16 g_wph[(size_t)Nq * Nq];  // w_proj^T split [n][k]
__device__ __align__(16) __nv_bfloat16 g_wpl[(size_t)Nq * Nq];
__device__ __align__(16) __nv_bfloat16 g_ch[(size_t)MB * Nq];   // ctx split
__device__ __align__(16) __nv_bfloat16 g_cl[(size_t)MB * Nq];

// ---------------- f32x2 packed helpers -------------------------------------
__device__ __forceinline__ unsigned long long bcast2(float v) {
    unsigned long long r;
    asm("mov.b64 %0, {%1, %1};" : "=l"(r) : "f"(v));
    return r;
}
__device__ __forceinline__ void fma2(unsigned long long& d,
                                     unsigned long long a, unsigned long long b) {
    asm("fma.rn.f32x2 %0, %1, %2, %0;" : "+l"(d) : "l"(a), "l"(b));
}
__device__ __forceinline__ void mul2(unsigned long long& d, unsigned long long a) {
    asm("mul.rn.f32x2 %0, %0, %1;" : "+l"(d) : "l"(a));
}
__device__ __forceinline__ float2 unpk(unsigned long long v) {
    float2 r;
    r.x = __uint_as_float((unsigned)(v & 0xffffffffull));
    r.y = __uint_as_float((unsigned)(v >> 32));
    return r;
}

// ---------------- mma.sync plumbing (baseline PTX, no 'a' features) --------
__device__ __forceinline__ uint32_t smem_u32(const void* p) {
    uint32_t a;
    asm("{ .reg .u64 t; cvta.to.shared.u64 t, %1; cvt.u32.u64 %0, t; }"
        : "=r"(a) : "l"(p));
    return a;
}
__device__ __forceinline__ void cp16(uint32_t sa, const void* ga) {
    asm volatile("cp.async.cg.shared.global [%0], [%1], 16;"
                 :: "r"(sa), "l"(ga) : "memory");
}
__device__ __forceinline__ void cp_commit() {
    asm volatile("cp.async.commit_group;" ::: "memory");
}
template <int N>
__device__ __forceinline__ void cp_wait() {
    asm volatile("cp.async.wait_group %0;" :: "n"(N) : "memory");
}
__device__ __forceinline__ void ldm4(uint32_t* r, uint32_t addr) {
    asm volatile("ldmatrix.sync.aligned.m8n8.x4.shared.b16 {%0,%1,%2,%3}, [%4];"
                 : "=r"(r[0]), "=r"(r[1]), "=r"(r[2]), "=r"(r[3]) : "r"(addr));
}
__device__ __forceinline__ void mma16816(float* c, const uint32_t* a,
                                         uint32_t b0, uint32_t b1) {
    asm volatile(
        "mma.sync.aligned.m16n8k16.row.col.f32.bf16.bf16.f32 "
        "{%0,%1,%2,%3}, {%4,%5,%6,%7}, {%8,%9}, {%0,%1,%2,%3};"
        : "+f"(c[0]), "+f"(c[1]), "+f"(c[2]), "+f"(c[3])
        : "r"(a[0]), "r"(a[1]), "r"(a[2]), "r"(a[3]), "r"(b0), "r"(b1));
}

// ---------------- conversion kernels ----------------------------------------
__global__ void split_kernel(const float* __restrict__ src,
                             __nv_bfloat16* __restrict__ hi,
                             __nv_bfloat16* __restrict__ lo, int n) {
    int i = blockIdx.x * 256 + threadIdx.x;
    if (i < n) {
        float v = src[i];
        __nv_bfloat16 h = __float2bfloat16(v);
        hi[i] = h;
        lo[i] = __float2bfloat16(v - __bfloat162float(h));
    }
}

// W [K][N] fp32 -> Wt hi/lo [N][K] bf16
__global__ void splitT_kernel(const float* __restrict__ W,
                              __nv_bfloat16* __restrict__ hT,
                              __nv_bfloat16* __restrict__ lT, int K, int N) {
    __shared__ float t[32][33];
    int n0 = blockIdx.x * 32, k0 = blockIdx.y * 32;
    int tx = threadIdx.x, ty = threadIdx.y;  // 32 x 8
    #pragma unroll
    for (int i = 0; i < 32; i += 8)
        t[ty + i][tx] = W[(size_t)(k0 + ty + i) * N + n0 + tx];
    __syncthreads();
    #pragma unroll
    for (int i = 0; i < 32; i += 8) {
        float v = t[tx][ty + i];
        __nv_bfloat16 h = __float2bfloat16(v);
        size_t o = (size_t)(n0 + ty + i) * K + k0 + tx;
        hT[o] = h;
        lT[o] = __float2bfloat16(v - __bfloat162float(h));
    }
}

// ---------------------------------------------------------------------------
// Tensor-core GEMM via mma.sync (bf16x3 emulated fp32):
//   C[M,N] = A@W^T + bias,  A hi/lo [M][1024] bf16, B hi/lo [N][1024] bf16.
// Block 128x128x32, 8 warps (warp tile 64x32), double-buffered cp.async.
// ---------------------------------------------------------------------------
#define LDK 40                       // padded smem row (bf16): conflict-free
#define MAT_ELEMS (128 * LDK)        // 5120 bf16 per matrix tile
#define STG_ELEMS (4 * MAT_ELEMS)    // Ah, Al, Bh, Bl
#define KTILES (Nq / 32)             // 32

__global__ __launch_bounds__(256, 2)
void gemm_mma(const __nv_bfloat16* __restrict__ Ah, const __nv_bfloat16* __restrict__ Al,
              const __nv_bfloat16* __restrict__ Bh, const __nv_bfloat16* __restrict__ Bl,
              const float* __restrict__ bias, float* __restrict__ C, int N) {
    extern __shared__ __nv_bfloat16 sm[];
    const int tid = threadIdx.x;
    const int lane = tid & 31, wid = tid >> 5;
    const int wm = wid & 1, wn = wid >> 1;            // warp tile: 64 x 32
    const int bm0 = blockIdx.y * 128, bn0 = blockIdx.x * 128;
    const uint32_t sbase = smem_u32(sm);

    const __nv_bfloat16* srcs[4] = {
        Ah + (size_t)bm0 * Nq, Al + (size_t)bm0 * Nq,
        Bh + (size_t)bn0 * Nq, Bl + (size_t)bn0 * Nq };

    // per-thread load mapping: 2 chunks of 16B per matrix per stage
    const int r_a = tid >> 2;            // base row for it=0 (lin>>2)
    const int c_a = tid & 3;             // 16B chunk within row

    float acc[4][4][4];
    #pragma unroll
    for (int i = 0; i < 4; i++)
        #pragma unroll
        for (int j = 0; j < 4; j++)
            #pragma unroll
            for (int k = 0; k < 4; k++) acc[i][j][k] = 0.0f;

    // ---- issue stage loads ----
    auto issue = [&](int buf, int kt) {
        uint32_t sb = sbase + (uint32_t)(buf * STG_ELEMS) * 2;
        #pragma unroll
        for (int mi = 0; mi < 4; mi++) {
            #pragma unroll
            for (int it = 0; it < 2; it++) {
                int r = r_a + it * 64;
                uint32_t sa = sb + (uint32_t)(mi * MAT_ELEMS + r * LDK + c_a * 8) * 2;
                cp16(sa, srcs[mi] + (size_t)r * Nq + kt * 32 + c_a * 8);
            }
        }
        cp_commit();
    };

    issue(0, 0);
    int buf = 0;

    // ldmatrix per-lane offsets
    const int aRow = wm * 64 + (lane & 15);
    const int aColL = (lane >> 4) * 8;
    const int bRow = wn * 32 + (lane & 7) + ((lane >> 4) << 3);
    const int bColL = ((lane >> 3) & 1) * 8;

    for (int kt = 0; kt < KTILES; kt++) {
        if (kt + 1 < KTILES) { issue(buf ^ 1, kt + 1); cp_wait<1>(); }
        else                 { cp_wait<0>(); }
        __syncthreads();

        uint32_t stg = sbase + (uint32_t)(buf * STG_ELEMS) * 2;
        uint32_t AHb = stg;
        uint32_t ALb = stg + (uint32_t)MAT_ELEMS * 2;
        uint32_t BHb = stg + (uint32_t)(2 * MAT_ELEMS) * 2;
        uint32_t BLb = stg + (uint32_t)(3 * MAT_ELEMS) * 2;

        #pragma unroll
        for (int ks = 0; ks < 2; ks++) {
            int kc = ks * 16;
            uint32_t ah[4][4], al[4][4], bh[2][4], bl[2][4];
            #pragma unroll
            for (int mt = 0; mt < 4; mt++)
                ldm4(ah[mt], AHb + (uint32_t)((aRow + mt * 16) * LDK + kc + aColL) * 2);
            #pragma unroll
            for (int p = 0; p < 2; p++)
                ldm4(bh[p], BHb + (uint32_t)((bRow + p * 16) * LDK + kc + bColL) * 2);

            // Ah . Bh
            #pragma unroll
            for (int mt = 0; mt < 4; mt++)
                #pragma unroll
                for (int nt = 0; nt < 4; nt++)
                    mma16816(acc[mt][nt], ah[mt], bh[nt >> 1][(nt & 1) * 2],
                             bh[nt >> 1][(nt & 1) * 2 + 1]);

            #pragma unroll
            for (int mt = 0; mt < 4; mt++)
                ldm4(al[mt], ALb + (uint32_t)((aRow + mt * 16) * LDK + kc + aColL) * 2);
            // Al . Bh
            #pragma unroll
            for (int mt = 0; mt < 4; mt++)
                #pragma unroll
                for (int nt = 0; nt < 4; nt++)
                    mma16816(acc[mt][nt], al[mt], bh[nt >> 1][(nt & 1) * 2],
                             bh[nt >> 1][(nt & 1) * 2 + 1]);

            #pragma unroll
            for (int p = 0; p < 2; p++)
                ldm4(bl[p], BLb + (uint32_t)((bRow + p * 16) * LDK + kc + bColL) * 2);
            // Ah . Bl
            #pragma unroll
            for (int mt = 0; mt < 4; mt++)
                #pragma unroll
                for (int nt = 0; nt < 4; nt++)
                    mma16816(acc[mt][nt], ah[mt], bl[nt >> 1][(nt & 1) * 2],
                             bl[nt >> 1][(nt & 1) * 2 + 1]);
        }
        __syncthreads();
        buf ^= 1;
    }

    // ---- epilogue: + bias, fp32 out ----
    const int lr = lane >> 2, lc = lane & 3;
    #pragma unroll
    for (int mt = 0; mt < 4; mt++) {
        int row0 = bm0 + wm * 64 + mt * 16 + lr;
        #pragma unroll
        for (int nt = 0; nt < 4; nt++) {
            int col = bn0 + wn * 32 + nt * 8 + lc * 2;
            float2 bi = *(const float2*)&bias[col];
            float2 o0 = {acc[mt][nt][0] + bi.x, acc[mt][nt][1] + bi.y};
            float2 o1 = {acc[mt][nt][2] + bi.x, acc[mt][nt][3] + bi.y};
            *(float2*)&C[(size_t)row0 * N + col] = o0;
            *(float2*)&C[(size_t)(row0 + 8) * N + col] = o1;
        }
    }
}

// ---------------- causal flash attention (Q in registers, KB=32) ------------
#define BQ 128
#define KB 32

__global__ __launch_bounds__(BQ)
void attn_kernel() {
    int bh = blockIdx.y;
    int b = bh >> 4;
    int h = bh & 15;
    int q0 = blockIdx.x * BQ;
    int tid = threadIdx.x;

    __shared__ __align__(16) float Ks[KB][Dd];
    __shared__ __align__(16) float Vs[KB][Dd];

    const float scale = 0.125f;
    const float* kbase = g_qkv + ((size_t)(b * Mq)) * N3 + Nq + h * Dd;
    const float* vbase = g_qkv + ((size_t)(b * Mq)) * N3 + 2 * Nq + h * Dd;

    int qi = q0 + tid;

    unsigned long long Q2[32];
    {
        const ulonglong2* qp = (const ulonglong2*)(g_qkv + ((size_t)(b * Mq + qi)) * N3 + h * Dd);
        #pragma unroll
        for (int t = 0; t < 16; t++) {
            ulonglong2 v = qp[t];
            Q2[2 * t] = v.x;
            Q2[2 * t + 1] = v.y;
        }
    }

    float mrun = -1e30f, lsum = 0.0f;
    unsigned long long O2[32];
    #pragma unroll
    for (int k = 0; k < 32; k++) O2[k] = 0ull;

    int nkb = (q0 + BQ) / KB;

    for (int kb = 0; kb < nkb; kb++) {
        int kstart = kb * KB;
        __syncthreads();
        #pragma unroll
        for (int it = 0; it < 4; it++) {
            int lin = it * BQ + tid;
            int r = lin >> 4;
            int c4 = (lin & 15) * 4;
            *(float4*)&Ks[r][c4] = *(const float4*)&kbase[(size_t)(kstart + r) * N3 + c4];
            *(float4*)&Vs[r][c4] = *(const float4*)&vbase[(size_t)(kstart + r) * N3 + c4];
        }
        __syncthreads();

        float s[KB];
        #pragma unroll
        for (int j = 0; j < KB; j += 2) {
            unsigned long long a0 = 0, b0 = 0, a1 = 0, b1 = 0;
            const ulonglong2* k0p = (const ulonglong2*)&Ks[j][0];
            const ulonglong2* k1p = (const ulonglong2*)&Ks[j + 1][0];
            #pragma unroll
            for (int t = 0; t < 16; t++) {
                ulonglong2 k0v = k0p[t];
                ulonglong2 k1v = k1p[t];
                fma2(a0, Q2[2 * t], k0v.x);
                fma2(b0, Q2[2 * t + 1], k0v.y);
                fma2(a1, Q2[2 * t], k1v.x);
                fma2(b1, Q2[2 * t + 1], k1v.y);
            }
            float2 r0 = unpk(a0), r1 = unpk(b0);
            float2 r2 = unpk(a1), r3 = unpk(b1);
            s[j]     = (r0.x + r0.y + r1.x + r1.y) * scale;
            s[j + 1] = (r2.x + r2.y + r3.x + r3.y) * scale;
        }

        float bmax = mrun;
        #pragma unroll
        for (int j = 0; j < KB; j++)
            if (kstart + j <= qi) bmax = fmaxf(bmax, s[j]);
        float corr = __expf(mrun - bmax);
        mrun = bmax;

        float e[KB];
        float esum = 0.0f;
        #pragma unroll
        for (int j = 0; j < KB; j++) {
            e[j] = (kstart + j <= qi) ? __expf(s[j] - mrun) : 0.0f;
            esum += e[j];
        }
        lsum = lsum * corr + esum;

        unsigned long long c2 = bcast2(corr);
        #pragma unroll
        for (int k = 0; k < 32; k++) mul2(O2[k], c2);

        #pragma unroll
        for (int j = 0; j < KB; j++) {
            unsigned long long p2 = bcast2(e[j]);
            const ulonglong2* vp = (const ulonglong2*)&Vs[j][0];
            #pragma unroll
            for (int t = 0; t < 16; t++) {
                ulonglong2 v = vp[t];
                fma2(O2[2 * t], p2, v.x);
                fma2(O2[2 * t + 1], p2, v.y);
            }
        }
    }

    float inv = 1.0f / lsum;
    size_t ob = (size_t)(b * Mq + qi) * Nq + h * Dd;
    __nv_bfloat16* ch = g_ch + ob;
    __nv_bfloat16* cl = g_cl + ob;
    #pragma unroll
    for (int dp = 0; dp < 32; dp++) {
        float2 t = unpk(O2[dp]);
        float o0 = t.x * inv, o1 = t.y * inv;
        __nv_bfloat16 h0 = __float2bfloat16(o0);
        __nv_bfloat16 h1 = __float2bfloat16(o1);
        __nv_bfloat162 hv; hv.x = h0; hv.y = h1;
        __nv_bfloat162 lv;
        lv.x = __float2bfloat16(o0 - __bfloat162float(h0));
        lv.y = __float2bfloat16(o1 - __bfloat162float(h1));
        *(__nv_bfloat162*)&ch[2 * dp] = hv;
        *(__nv_bfloat162*)&cl[2 * dp] = lv;
    }
}

// ---------------------------------------------------------------------------
extern "C" void kernel_launch(void* const* d_in, const int* in_sizes, int n_in,
                              void* d_out, int out_size) {
    const float* x      = (const float*)d_in[0];
    const float* w_attn = (const float*)d_in[1];
    const float* w_proj = (const float*)d_in[2];
    const float* b_attn = (const float*)d_in[3];
    const float* b_proj = (const float*)d_in[4];
    float* out = (float*)d_out;

    float* qkv = nullptr;
    __nv_bfloat16 *xh, *xl, *wah, *wal, *wph, *wpl, *ch, *cl;
    cudaGetSymbolAddress((void**)&qkv, g_qkv);
    cudaGetSymbolAddress((void**)&xh, g_xh);
    cudaGetSymbolAddress((void**)&xl, g_xl);
    cudaGetSymbolAddress((void**)&wah, g_wah);
    cudaGetSymbolAddress((void**)&wal, g_wal);
    cudaGetSymbolAddress((void**)&wph, g_wph);
    cudaGetSymbolAddress((void**)&wpl, g_wpl);
    cudaGetSymbolAddress((void**)&ch, g_ch);
    cudaGetSymbolAddress((void**)&cl, g_cl);

    static bool attr_set = false;
    if (!attr_set) {
        cudaFuncSetAttribute(gemm_mma, cudaFuncAttributeMaxDynamicSharedMemorySize,
                             2 * STG_ELEMS * 2);
        attr_set = true;
    }

    // --- operand conversions (bf16 hi/lo splits) ---
    {
        int n = MB * Nq;
        split_kernel<<<(n + 255) / 256, 256>>>(x, xh, xl, n);
    }
    splitT_kernel<<<dim3(N3 / 32, Nq / 32), dim3(32, 8)>>>(w_attn, wah, wal, Nq, N3);
    splitT_kernel<<<dim3(Nq / 32, Nq / 32), dim3(32, 8)>>>(w_proj, wph, wpl, Nq, Nq);

    // --- QKV projection: [4096,1024] @ [1024,3072] + b_attn -> g_qkv ---
    gemm_mma<<<dim3(N3 / 128, MB / 128), 256, 2 * STG_ELEMS * 2>>>(
        xh, xl, wah, wal, b_attn, qkv, N3);

    // --- causal attention -> ctx (bf16 hi/lo) ---
    attn_kernel<<<dim3(Mq / BQ, Bq * Hh), BQ>>>();

    // --- output projection: [4096,1024] @ [1024,1024] + b_proj -> out ---
    gemm_mma<<<dim3(Nq / 128, MB / 128), 256, 2 * STG_ELEMS * 2>>>(
        ch, cl, wph, wpl, b_proj, out, Nq);
}

// round 6
// speedup vs baseline: 4.2708x; 2.0096x over previous
#include <cuda_runtime.h>
#include <cuda_bf16.h>
#include <cstdint>
#include <math.h>

#define Bq 2
#define Mq 2048
#define Nq 1024
#define Hh 16
#define Dd 64
#define N3 3072
#define MB (Bq*Mq)

// ---------------- scratch (device globals; no cudaMalloc allowed) ----------
__device__ __align__(16) __nv_bfloat16 g_qkvh[(size_t)MB * N3]; // qkv hi
__device__ __align__(16) __nv_bfloat16 g_qkvl[(size_t)MB * N3]; // qkv lo
__device__ __align__(16) __nv_bfloat16 g_xh[(size_t)MB * Nq];
__device__ __align__(16) __nv_bfloat16 g_xl[(size_t)MB * Nq];
__device__ __align__(16) __nv_bfloat16 g_wah[(size_t)N3 * Nq];  // w_attn^T [n][k]
__device__ __align__(16) __nv_bfloat16 g_wal[(size_t)N3 * Nq];
__device__ __align__(16) __nv_bfloat16 g_wph[(size_t)Nq * Nq];  // w_proj^T [n][k]
__device__ __align__(16) __nv_bfloat16 g_wpl[(size_t)Nq * Nq];
__device__ __align__(16) __nv_bfloat16 g_ch[(size_t)MB * Nq];   // ctx hi
__device__ __align__(16) __nv_bfloat16 g_cl[(size_t)MB * Nq];   // ctx lo

// ---------------- PTX plumbing (baseline sm_103, no 'a' features) ----------
__device__ __forceinline__ uint32_t smem_u32(const void* p) {
    uint32_t a;
    asm("{ .reg .u64 t; cvta.to.shared.u64 t, %1; cvt.u32.u64 %0, t; }"
        : "=r"(a) : "l"(p));
    return a;
}
__device__ __forceinline__ void cp16(uint32_t sa, const void* ga) {
    asm volatile("cp.async.cg.shared.global [%0], [%1], 16;"
                 :: "r"(sa), "l"(ga) : "memory");
}
__device__ __forceinline__ void cp_commit() {
    asm volatile("cp.async.commit_group;" ::: "memory");
}
template <int N>
__device__ __forceinline__ void cp_wait() {
    asm volatile("cp.async.wait_group %0;" :: "n"(N) : "memory");
}
__device__ __forceinline__ void ldm4(uint32_t* r, uint32_t addr) {
    asm volatile("ldmatrix.sync.aligned.m8n8.x4.shared.b16 {%0,%1,%2,%3}, [%4];"
                 : "=r"(r[0]), "=r"(r[1]), "=r"(r[2]), "=r"(r[3]) : "r"(addr));
}
__device__ __forceinline__ void ldm4t(uint32_t* r, uint32_t addr) {
    asm volatile("ldmatrix.sync.aligned.m8n8.x4.trans.shared.b16 {%0,%1,%2,%3}, [%4];"
                 : "=r"(r[0]), "=r"(r[1]), "=r"(r[2]), "=r"(r[3]) : "r"(addr));
}
__device__ __forceinline__ void mma16816(float* c, const uint32_t* a,
                                         uint32_t b0, uint32_t b1) {
    asm volatile(
        "mma.sync.aligned.m16n8k16.row.col.f32.bf16.bf16.f32 "
        "{%0,%1,%2,%3}, {%4,%5,%6,%7}, {%8,%9}, {%0,%1,%2,%3};"
        : "+f"(c[0]), "+f"(c[1]), "+f"(c[2]), "+f"(c[3])
        : "r"(a[0]), "r"(a[1]), "r"(a[2]), "r"(a[3]), "r"(b0), "r"(b1));
}
// packed bf16x2 from two f32 (second operand -> low half)
__device__ __forceinline__ uint32_t cvt2(float hi, float lo) {
    uint32_t r;
    asm("cvt.rn.bf16x2.f32 %0, %1, %2;" : "=r"(r) : "f"(hi), "f"(lo));
    return r;
}
// fast exp on FMA pipe (magic-round exp2, err ~2.4e-6 rel)
__device__ __forceinline__ float fexp(float x) {
    float t = x * 1.4426950408889634f;
    t = fmaxf(t, -125.0f);
    float z = t + 12582912.0f;           // round-to-nearest int
    int iz = __float_as_int(z);
    float fi = z - 12582912.0f;
    float f = t - fi;                    // [-0.5, 0.5]
    float p = 0.00133335581f;
    p = fmaf(p, f, 0.00961812911f);
    p = fmaf(p, f, 0.05550410866f);
    p = fmaf(p, f, 0.24022650700f);
    p = fmaf(p, f, 0.69314718056f);
    p = fmaf(p, f, 1.0f);
    return __int_as_float(__float_as_int(p) + (iz << 23));
}

// ---------------- conversion kernels ----------------------------------------
__global__ void split_kernel(const float* __restrict__ src,
                             __nv_bfloat16* __restrict__ hi,
                             __nv_bfloat16* __restrict__ lo, int n) {
    int i = blockIdx.x * 256 + threadIdx.x;
    if (i < n) {
        float v = src[i];
        __nv_bfloat16 h = __float2bfloat16(v);
        hi[i] = h;
        lo[i] = __float2bfloat16(v - __bfloat162float(h));
    }
}
__global__ void splitT_kernel(const float* __restrict__ W,
                              __nv_bfloat16* __restrict__ hT,
                              __nv_bfloat16* __restrict__ lT, int K, int N) {
    __shared__ float t[32][33];
    int n0 = blockIdx.x * 32, k0 = blockIdx.y * 32;
    int tx = threadIdx.x, ty = threadIdx.y;
    #pragma unroll
    for (int i = 0; i < 32; i += 8)
        t[ty + i][tx] = W[(size_t)(k0 + ty + i) * N + n0 + tx];
    __syncthreads();
    #pragma unroll
    for (int i = 0; i < 32; i += 8) {
        float v = t[tx][ty + i];
        __nv_bfloat16 h = __float2bfloat16(v);
        size_t o = (size_t)(n0 + ty + i) * K + k0 + tx;
        hT[o] = h;
        lT[o] = __float2bfloat16(v - __bfloat162float(h));
    }
}

// ---------------------------------------------------------------------------
// Tensor-core GEMM (bf16x3 emulated fp32): C = A@W^T + bias.
// 128x128x32 block, 8 warps (64x32 warp tile), double-buffered cp.async.
// Epilogue: fp32 out (Cf) OR bf16 hi/lo split out (Ch/Cl).
// ---------------------------------------------------------------------------
#define LDK 40
#define MAT_ELEMS (128 * LDK)
#define STG_ELEMS (4 * MAT_ELEMS)
#define KTILES (Nq / 32)

__global__ __launch_bounds__(256, 2)
void gemm_mma(const __nv_bfloat16* __restrict__ Ah, const __nv_bfloat16* __restrict__ Al,
              const __nv_bfloat16* __restrict__ Bh, const __nv_bfloat16* __restrict__ Bl,
              const float* __restrict__ bias,
              float* __restrict__ Cf,
              __nv_bfloat16* __restrict__ Ch, __nv_bfloat16* __restrict__ Cl,
              int N) {
    extern __shared__ __nv_bfloat16 sm[];
    const int tid = threadIdx.x;
    const int lane = tid & 31, wid = tid >> 5;
    const int wm = wid & 1, wn = wid >> 1;
    const int bm0 = blockIdx.y * 128, bn0 = blockIdx.x * 128;
    const uint32_t sbase = smem_u32(sm);

    const __nv_bfloat16* srcs[4] = {
        Ah + (size_t)bm0 * Nq, Al + (size_t)bm0 * Nq,
        Bh + (size_t)bn0 * Nq, Bl + (size_t)bn0 * Nq };

    const int r_a = tid >> 2;
    const int c_a = tid & 3;

    float acc[4][4][4];
    #pragma unroll
    for (int i = 0; i < 4; i++)
        #pragma unroll
        for (int j = 0; j < 4; j++)
            #pragma unroll
            for (int k = 0; k < 4; k++) acc[i][j][k] = 0.0f;

    auto issue = [&](int buf, int kt) {
        uint32_t sb = sbase + (uint32_t)(buf * STG_ELEMS) * 2;
        #pragma unroll
        for (int mi = 0; mi < 4; mi++) {
            #pragma unroll
            for (int it = 0; it < 2; it++) {
                int r = r_a + it * 64;
                uint32_t sa = sb + (uint32_t)(mi * MAT_ELEMS + r * LDK + c_a * 8) * 2;
                cp16(sa, srcs[mi] + (size_t)r * Nq + kt * 32 + c_a * 8);
            }
        }
        cp_commit();
    };

    issue(0, 0);
    int buf = 0;

    const int aRow = wm * 64 + (lane & 15);
    const int aColL = (lane >> 4) * 8;
    const int bRow = wn * 32 + (lane & 7) + ((lane >> 4) << 3);
    const int bColL = ((lane >> 3) & 1) * 8;

    for (int kt = 0; kt < KTILES; kt++) {
        if (kt + 1 < KTILES) { issue(buf ^ 1, kt + 1); cp_wait<1>(); }
        else                 { cp_wait<0>(); }
        __syncthreads();

        uint32_t stg = sbase + (uint32_t)(buf * STG_ELEMS) * 2;
        uint32_t AHb = stg;
        uint32_t ALb = stg + (uint32_t)MAT_ELEMS * 2;
        uint32_t BHb = stg + (uint32_t)(2 * MAT_ELEMS) * 2;
        uint32_t BLb = stg + (uint32_t)(3 * MAT_ELEMS) * 2;

        #pragma unroll
        for (int ks = 0; ks < 2; ks++) {
            int kc = ks * 16;
            uint32_t ah[4][4], al[4][4], bh[2][4], bl[2][4];
            #pragma unroll
            for (int mt = 0; mt < 4; mt++)
                ldm4(ah[mt], AHb + (uint32_t)((aRow + mt * 16) * LDK + kc + aColL) * 2);
            #pragma unroll
            for (int p = 0; p < 2; p++)
                ldm4(bh[p], BHb + (uint32_t)((bRow + p * 16) * LDK + kc + bColL) * 2);
            #pragma unroll
            for (int mt = 0; mt < 4; mt++)
                #pragma unroll
                for (int nt = 0; nt < 4; nt++)
                    mma16816(acc[mt][nt], ah[mt], bh[nt >> 1][(nt & 1) * 2],
                             bh[nt >> 1][(nt & 1) * 2 + 1]);
            #pragma unroll
            for (int mt = 0; mt < 4; mt++)
                ldm4(al[mt], ALb + (uint32_t)((aRow + mt * 16) * LDK + kc + aColL) * 2);
            #pragma unroll
            for (int mt = 0; mt < 4; mt++)
                #pragma unroll
                for (int nt = 0; nt < 4; nt++)
                    mma16816(acc[mt][nt], al[mt], bh[nt >> 1][(nt & 1) * 2],
                             bh[nt >> 1][(nt & 1) * 2 + 1]);
            #pragma unroll
            for (int p = 0; p < 2; p++)
                ldm4(bl[p], BLb + (uint32_t)((bRow + p * 16) * LDK + kc + bColL) * 2);
            #pragma unroll
            for (int mt = 0; mt < 4; mt++)
                #pragma unroll
                for (int nt = 0; nt < 4; nt++)
                    mma16816(acc[mt][nt], ah[mt], bl[nt >> 1][(nt & 1) * 2],
                             bl[nt >> 1][(nt & 1) * 2 + 1]);
        }
        __syncthreads();
        buf ^= 1;
    }

    const int lr = lane >> 2, lc = lane & 3;
    #pragma unroll
    for (int mt = 0; mt < 4; mt++) {
        int row0 = bm0 + wm * 64 + mt * 16 + lr;
        #pragma unroll
        for (int nt = 0; nt < 4; nt++) {
            int col = bn0 + wn * 32 + nt * 8 + lc * 2;
            float2 bi = *(const float2*)&bias[col];
            float v00 = acc[mt][nt][0] + bi.x, v01 = acc[mt][nt][1] + bi.y;
            float v10 = acc[mt][nt][2] + bi.x, v11 = acc[mt][nt][3] + bi.y;
            if (Cf) {
                float2 o0 = {v00, v01}, o1 = {v10, v11};
                *(float2*)&Cf[(size_t)row0 * N + col] = o0;
                *(float2*)&Cf[(size_t)(row0 + 8) * N + col] = o1;
            } else {
                uint32_t h0 = cvt2(v01, v00);
                uint32_t h1 = cvt2(v11, v10);
                float r00 = v00 - __int_as_float(h0 << 16);
                float r01 = v01 - __int_as_float(h0 & 0xffff0000u);
                float r10 = v10 - __int_as_float(h1 << 16);
                float r11 = v11 - __int_as_float(h1 & 0xffff0000u);
                *(uint32_t*)&Ch[(size_t)row0 * N + col] = h0;
                *(uint32_t*)&Ch[(size_t)(row0 + 8) * N + col] = h1;
                *(uint32_t*)&Cl[(size_t)row0 * N + col] = cvt2(r01, r00);
                *(uint32_t*)&Cl[(size_t)(row0 + 8) * N + col] = cvt2(r11, r10);
            }
        }
    }
}

// ---------------------------------------------------------------------------
// Tensor-core causal flash attention (FA2-style, bf16 hi/lo splits).
// CTA: 128 q-rows x d=64, 8 warps x 16 rows. 64-key tiles, double buffered.
// ---------------------------------------------------------------------------
#define AQ 128
#define AKT 64
#define LDA 72
#define Q_ELEMS (2 * 128 * LDA)          // Qh + Ql
#define KV_STG  (4 * 64 * LDA)           // Kh,Kl,Vh,Vl per stage
#define ATT_SMEM ((Q_ELEMS + 2 * KV_STG) * 2)  // bytes = 110592

__global__ __launch_bounds__(256)
void attn_mma() {
    extern __shared__ __nv_bfloat16 sm[];
    const int tid = threadIdx.x, lane = tid & 31, wid = tid >> 5;
    const int bh = blockIdx.y, b = bh >> 4, h = bh & 15;
    const int qt = gridDim.x - 1 - blockIdx.x;   // heavy tiles first
    const int q0 = qt * AQ;
    const uint32_t sbase = smem_u32(sm);
    const size_t rowb = (size_t)b * Mq;

    // smem element offsets
    const uint32_t oQh = 0, oQl = 128 * LDA, oKV = Q_ELEMS;

    // ---- load Q tile (hi/lo) ----
    #pragma unroll
    for (int l = tid; l < 2048; l += 256) {
        int arr = l >> 10;               // 0:h 1:l
        int r = (l >> 3) & 127;
        int c = l & 7;
        const __nv_bfloat16* g = (arr ? g_qkvl : g_qkvh) +
            (rowb + q0 + r) * N3 + h * 64 + c * 8;
        cp16(sbase + ((arr ? oQl : oQh) + r * LDA + c * 8) * 2, g);
    }
    cp_commit();

    auto load_kv = [&](int stg, int j0) {
        uint32_t base = oKV + stg * KV_STG;
        #pragma unroll
        for (int l = tid; l < 2048; l += 256) {
            int arr = l >> 9;            // 0:Kh 1:Kl 2:Vh 3:Vl
            int r = (l >> 3) & 63;
            int c = l & 7;
            size_t roff = (rowb + j0 + r) * N3 + h * 64 + c * 8;
            const __nv_bfloat16* g =
                (arr == 0) ? g_qkvh + roff + Nq :
                (arr == 1) ? g_qkvl + roff + Nq :
                (arr == 2) ? g_qkvh + roff + 2 * Nq :
                             g_qkvl + roff + 2 * Nq;
            cp16(sbase + (base + arr * 64 * LDA + r * LDA + c * 8) * 2, g);
        }
        cp_commit();
    };

    load_kv(0, 0);

    // ---- Q fragments into registers (once) ----
    cp_wait<1>();          // Q group done (stage0 may still be pending)
    __syncthreads();
    uint32_t qhf[4][4], qlf[4][4];
    {
        int aRow = wid * 16 + (lane & 15);
        int aCol = (lane >> 4) * 8;
        #pragma unroll
        for (int ks = 0; ks < 4; ks++) {
            ldm4(qhf[ks], sbase + (oQh + aRow * LDA + ks * 16 + aCol) * 2);
            ldm4(qlf[ks], sbase + (oQl + aRow * LDA + ks * 16 + aCol) * 2);
        }
    }

    float m0 = -1e30f, m1 = -1e30f, l0 = 0.0f, l1 = 0.0f;
    float O[8][4];
    #pragma unroll
    for (int f = 0; f < 8; f++)
        #pragma unroll
        for (int c = 0; c < 4; c++) O[f][c] = 0.0f;

    const int nkt = (q0 + AQ) / AKT;
    int buf = 0;
    const float scale = 0.125f;
    const int rbase0 = q0 + wid * 16 + (lane >> 2);

    for (int kt = 0; kt < nkt; kt++) {
        const int j0 = kt * AKT;
        if (kt + 1 < nkt) { load_kv(buf ^ 1, j0 + AKT); cp_wait<1>(); }
        else              { cp_wait<0>(); }
        __syncthreads();

        const uint32_t stg = oKV + buf * KV_STG;
        const uint32_t sKh = sbase + stg * 2;
        const uint32_t sKl = sKh + (uint32_t)(64 * LDA) * 2;
        const uint32_t sVh = sKl + (uint32_t)(64 * LDA) * 2;
        const uint32_t sVl = sVh + (uint32_t)(64 * LDA) * 2;

        // ---- scores = Q K^T (3 split products) ----
        float s[8][4];
        #pragma unroll
        for (int f = 0; f < 8; f++)
            #pragma unroll
            for (int c = 0; c < 4; c++) s[f][c] = 0.0f;

        const int kRow = (lane & 7) + ((lane >> 4) << 3);
        const int kCol = ((lane >> 3) & 1) * 8;
        #pragma unroll
        for (int ks = 0; ks < 4; ks++) {
            #pragma unroll
            for (int p = 0; p < 4; p++) {
                uint32_t addr = sKh + (uint32_t)((p * 16 + kRow) * LDA + ks * 16 + kCol) * 2;
                uint32_t kh4[4], kl4[4];
                ldm4(kh4, addr);
                ldm4(kl4, addr + (uint32_t)(64 * LDA) * 2);  // Kl same offset
                mma16816(s[2 * p],     qhf[ks], kh4[0], kh4[1]);
                mma16816(s[2 * p + 1], qhf[ks], kh4[2], kh4[3]);
                mma16816(s[2 * p],     qhf[ks], kl4[0], kl4[1]);
                mma16816(s[2 * p + 1], qhf[ks], kl4[2], kl4[3]);
                mma16816(s[2 * p],     qlf[ks], kh4[0], kh4[1]);
                mma16816(s[2 * p + 1], qlf[ks], kh4[2], kh4[3]);
            }
        }

        // ---- scale + causal mask (diagonal tiles only) ----
        if (j0 + AKT - 1 > q0) {
            #pragma unroll
            for (int f = 0; f < 8; f++) {
                int k0c = j0 + f * 8 + (lane & 3) * 2;
                #pragma unroll
                for (int c = 0; c < 4; c++) {
                    int key = k0c + (c & 1);
                    int row = rbase0 + ((c >> 1) * 8);
                    s[f][c] = (key > row) ? -1e30f : s[f][c] * scale;
                }
            }
        } else {
            #pragma unroll
            for (int f = 0; f < 8; f++)
                #pragma unroll
                for (int c = 0; c < 4; c++) s[f][c] *= scale;
        }

        // ---- online softmax ----
        float bm0 = -1e30f, bm1 = -1e30f;
        #pragma unroll
        for (int f = 0; f < 8; f++) {
            bm0 = fmaxf(bm0, fmaxf(s[f][0], s[f][1]));
            bm1 = fmaxf(bm1, fmaxf(s[f][2], s[f][3]));
        }
        bm0 = fmaxf(bm0, __shfl_xor_sync(0xffffffff, bm0, 1));
        bm0 = fmaxf(bm0, __shfl_xor_sync(0xffffffff, bm0, 2));
        bm1 = fmaxf(bm1, __shfl_xor_sync(0xffffffff, bm1, 1));
        bm1 = fmaxf(bm1, __shfl_xor_sync(0xffffffff, bm1, 2));
        float mn0 = fmaxf(m0, bm0), mn1 = fmaxf(m1, bm1);
        float corr0 = fexp(m0 - mn0), corr1 = fexp(m1 - mn1);
        m0 = mn0; m1 = mn1;

        float es0 = 0.0f, es1 = 0.0f;
        #pragma unroll
        for (int f = 0; f < 8; f++) {
            s[f][0] = fexp(s[f][0] - m0);
            s[f][1] = fexp(s[f][1] - m0);
            s[f][2] = fexp(s[f][2] - m1);
            s[f][3] = fexp(s[f][3] - m1);
            es0 += s[f][0] + s[f][1];
            es1 += s[f][2] + s[f][3];
        }
        es0 += __shfl_xor_sync(0xffffffff, es0, 1);
        es0 += __shfl_xor_sync(0xffffffff, es0, 2);
        es1 += __shfl_xor_sync(0xffffffff, es1, 1);
        es1 += __shfl_xor_sync(0xffffffff, es1, 2);
        l0 = l0 * corr0 + es0;
        l1 = l1 * corr1 + es1;

        #pragma unroll
        for (int f = 0; f < 8; f++) {
            O[f][0] *= corr0; O[f][1] *= corr0;
            O[f][2] *= corr1; O[f][3] *= corr1;
        }

        // ---- P @ V (3 split products) ----
        const int vRow = lane & 15;
        const int vCol = (lane >> 4) * 8;
        #pragma unroll
        for (int ks2 = 0; ks2 < 4; ks2++) {
            uint32_t ahf[4], alf[4];
            #pragma unroll
            for (int q = 0; q < 2; q++) {       // two C-frags -> a0/a1 and a2/a3
                float p0 = s[2 * ks2 + q][0], p1 = s[2 * ks2 + q][1];
                float p2 = s[2 * ks2 + q][2], p3 = s[2 * ks2 + q][3];
                uint32_t h01 = cvt2(p1, p0);
                uint32_t h23 = cvt2(p3, p2);
                ahf[2 * q + 0] = h01;
                ahf[2 * q + 1] = h23;
                float r0 = p0 - __int_as_float(h01 << 16);
                float r1 = p1 - __int_as_float(h01 & 0xffff0000u);
                float r2 = p2 - __int_as_float(h23 << 16);
                float r3 = p3 - __int_as_float(h23 & 0xffff0000u);
                alf[2 * q + 0] = cvt2(r1, r0);
                alf[2 * q + 1] = cvt2(r3, r2);
            }
            // NOTE: a-frag order must be {a0,a1,a2,a3} = {h of frag0 rows, frag0 rows+8,
            // frag1 rows, frag1 rows+8} -> reorder:
            uint32_t aH[4] = {ahf[0], ahf[1], ahf[2], ahf[3]};
            uint32_t aL[4] = {alf[0], alf[1], alf[2], alf[3]};
            #pragma unroll
            for (int p2i = 0; p2i < 4; p2i++) {
                uint32_t addr = sVh + (uint32_t)((vRow + ks2 * 16) * LDA + p2i * 16 + vCol) * 2;
                uint32_t vh4[4], vl4[4];
                ldm4t(vh4, addr);
                ldm4t(vl4, addr + (sVl - sVh));
                mma16816(O[2 * p2i],     aH, vh4[0], vh4[1]);
                mma16816(O[2 * p2i + 1], aH, vh4[2], vh4[3]);
                mma16816(O[2 * p2i],     aH, vl4[0], vl4[1]);
                mma16816(O[2 * p2i + 1], aH, vl4[2], vl4[3]);
                mma16816(O[2 * p2i],     aL, vh4[0], vh4[1]);
                mma16816(O[2 * p2i + 1], aL, vh4[2], vh4[3]);
            }
        }
        __syncthreads();
        buf ^= 1;
    }

    // ---- epilogue: normalize, write ctx bf16 hi/lo ----
    float inv0 = 1.0f / l0, inv1 = 1.0f / l1;
    int gr0 = rbase0;
    size_t base0 = (rowb + gr0) * Nq + h * 64;
    size_t base1 = (rowb + gr0 + 8) * Nq + h * 64;
    #pragma unroll
    for (int f = 0; f < 8; f++) {
        int col = f * 8 + (lane & 3) * 2;
        float v00 = O[f][0] * inv0, v01 = O[f][1] * inv0;
        float v10 = O[f][2] * inv1, v11 = O[f][3] * inv1;
        uint32_t h0 = cvt2(v01, v00);
        uint32_t h1 = cvt2(v11, v10);
        float r00 = v00 - __int_as_float(h0 << 16);
        float r01 = v01 - __int_as_float(h0 & 0xffff0000u);
        float r10 = v10 - __int_as_float(h1 << 16);
        float r11 = v11 - __int_as_float(h1 & 0xffff0000u);
        *(uint32_t*)&g_ch[base0 + col] = h0;
        *(uint32_t*)&g_cl[base0 + col] = cvt2(r01, r00);
        *(uint32_t*)&g_ch[base1 + col] = h1;
        *(uint32_t*)&g_cl[base1 + col] = cvt2(r11, r10);
    }
}

// ---------------------------------------------------------------------------
extern "C" void kernel_launch(void* const* d_in, const int* in_sizes, int n_in,
                              void* d_out, int out_size) {
    const float* x      = (const float*)d_in[0];
    const float* w_attn = (const float*)d_in[1];
    const float* w_proj = (const float*)d_in[2];
    const float* b_attn = (const float*)d_in[3];
    const float* b_proj = (const float*)d_in[4];
    float* out = (float*)d_out;

    __nv_bfloat16 *qh, *ql, *xh, *xl, *wah, *wal, *wph, *wpl, *ch, *cl;
    cudaGetSymbolAddress((void**)&qh, g_qkvh);
    cudaGetSymbolAddress((void**)&ql, g_qkvl);
    cudaGetSymbolAddress((void**)&xh, g_xh);
    cudaGetSymbolAddress((void**)&xl, g_xl);
    cudaGetSymbolAddress((void**)&wah, g_wah);
    cudaGetSymbolAddress((void**)&wal, g_wal);
    cudaGetSymbolAddress((void**)&wph, g_wph);
    cudaGetSymbolAddress((void**)&wpl, g_wpl);
    cudaGetSymbolAddress((void**)&ch, g_ch);
    cudaGetSymbolAddress((void**)&cl, g_cl);

    static bool attr_set = false;
    if (!attr_set) {
        cudaFuncSetAttribute(gemm_mma, cudaFuncAttributeMaxDynamicSharedMemorySize,
                             2 * STG_ELEMS * 2);
        cudaFuncSetAttribute(attn_mma, cudaFuncAttributeMaxDynamicSharedMemorySize,
                             ATT_SMEM);
        attr_set = true;
    }

    // conversions
    {
        int n = MB * Nq;
        split_kernel<<<(n + 255) / 256, 256>>>(x, xh, xl, n);
    }
    splitT_kernel<<<dim3(N3 / 32, Nq / 32), dim3(32, 8)>>>(w_attn, wah, wal, Nq, N3);
    splitT_kernel<<<dim3(Nq / 32, Nq / 32), dim3(32, 8)>>>(w_proj, wph, wpl, Nq, Nq);

    // QKV projection -> bf16 hi/lo qkv
    gemm_mma<<<dim3(N3 / 128, MB / 128), 256, 2 * STG_ELEMS * 2>>>(
        xh, xl, wah, wal, b_attn, nullptr, qh, ql, N3);

    // causal flash attention -> ctx hi/lo
    attn_mma<<<dim3(Mq / AQ, Bq * Hh), 256, ATT_SMEM>>>();

    // output projection -> fp32 out
    gemm_mma<<<dim3(Nq / 128, MB / 128), 256, 2 * STG_ELEMS * 2>>>(
        ch, cl, wph, wpl, b_proj, out, nullptr, nullptr, Nq);
}

// round 7
// speedup vs baseline: 4.2739x; 1.0007x over previous
#include <cuda_runtime.h>
#include <cuda_bf16.h>
#include <cstdint>
#include <math.h>

#define Bq 2
#define Mq 2048
#define Nq 1024
#define Hh 16
#define Dd 64
#define N3 3072
#define MB (Bq*Mq)

// ---------------- scratch (device globals; no cudaMalloc allowed) ----------
__device__ __align__(16) __nv_bfloat16 g_qkvh[(size_t)MB * N3]; // qkv hi
__device__ __align__(16) __nv_bfloat16 g_qkvl[(size_t)MB * N3]; // qkv lo
__device__ __align__(16) __nv_bfloat16 g_xh[(size_t)MB * Nq];
__device__ __align__(16) __nv_bfloat16 g_xl[(size_t)MB * Nq];
__device__ __align__(16) __nv_bfloat16 g_wah[(size_t)N3 * Nq];  // w_attn^T [n][k]
__device__ __align__(16) __nv_bfloat16 g_wal[(size_t)N3 * Nq];
__device__ __align__(16) __nv_bfloat16 g_wph[(size_t)Nq * Nq];  // w_proj^T [n][k]
__device__ __align__(16) __nv_bfloat16 g_wpl[(size_t)Nq * Nq];
__device__ __align__(16) __nv_bfloat16 g_ch[(size_t)MB * Nq];   // ctx hi
__device__ __align__(16) __nv_bfloat16 g_cl[(size_t)MB * Nq];   // ctx lo

// ---------------- PTX plumbing (baseline sm_103, no 'a' features) ----------
__device__ __forceinline__ uint32_t smem_u32(const void* p) {
    uint32_t a;
    asm("{ .reg .u64 t; cvta.to.shared.u64 t, %1; cvt.u32.u64 %0, t; }"
        : "=r"(a) : "l"(p));
    return a;
}
__device__ __forceinline__ void cp16(uint32_t sa, const void* ga) {
    asm volatile("cp.async.cg.shared.global [%0], [%1], 16;"
                 :: "r"(sa), "l"(ga) : "memory");
}
__device__ __forceinline__ void cp_commit() {
    asm volatile("cp.async.commit_group;" ::: "memory");
}
template <int N>
__device__ __forceinline__ void cp_wait() {
    asm volatile("cp.async.wait_group %0;" :: "n"(N) : "memory");
}
__device__ __forceinline__ void ldm4(uint32_t* r, uint32_t addr) {
    asm volatile("ldmatrix.sync.aligned.m8n8.x4.shared.b16 {%0,%1,%2,%3}, [%4];"
                 : "=r"(r[0]), "=r"(r[1]), "=r"(r[2]), "=r"(r[3]) : "r"(addr));
}
__device__ __forceinline__ void ldm4t(uint32_t* r, uint32_t addr) {
    asm volatile("ldmatrix.sync.aligned.m8n8.x4.trans.shared.b16 {%0,%1,%2,%3}, [%4];"
                 : "=r"(r[0]), "=r"(r[1]), "=r"(r[2]), "=r"(r[3]) : "r"(addr));
}
__device__ __forceinline__ void mma16816(float* c, const uint32_t* a,
                                         uint32_t b0, uint32_t b1) {
    asm volatile(
        "mma.sync.aligned.m16n8k16.row.col.f32.bf16.bf16.f32 "
        "{%0,%1,%2,%3}, {%4,%5,%6,%7}, {%8,%9}, {%0,%1,%2,%3};"
        : "+f"(c[0]), "+f"(c[1]), "+f"(c[2]), "+f"(c[3])
        : "r"(a[0]), "r"(a[1]), "r"(a[2]), "r"(a[3]), "r"(b0), "r"(b1));
}
// packed bf16x2 from two f32 (second operand -> low half)
__device__ __forceinline__ uint32_t cvt2(float hi, float lo) {
    uint32_t r;
    asm("cvt.rn.bf16x2.f32 %0, %1, %2;" : "=r"(r) : "f"(hi), "f"(lo));
    return r;
}
// fast exp on FMA pipe (magic-round exp2, err ~2.4e-6 rel)
__device__ __forceinline__ float fexp(float x) {
    float t = x * 1.4426950408889634f;
    t = fmaxf(t, -125.0f);
    float z = t + 12582912.0f;           // round-to-nearest int
    int iz = __float_as_int(z);
    float fi = z - 12582912.0f;
    float f = t - fi;                    // [-0.5, 0.5]
    float p = 0.00133335581f;
    p = fmaf(p, f, 0.00961812911f);
    p = fmaf(p, f, 0.05550410866f);
    p = fmaf(p, f, 0.24022650700f);
    p = fmaf(p, f, 0.69314718056f);
    p = fmaf(p, f, 1.0f);
    return __int_as_float(__float_as_int(p) + (iz << 23));
}

// ---------------- conversion kernels ----------------------------------------
__global__ void split_kernel(const float* __restrict__ src,
                             __nv_bfloat16* __restrict__ hi,
                             __nv_bfloat16* __restrict__ lo, int n) {
    int i = blockIdx.x * 256 + threadIdx.x;
    if (i < n) {
        float v = src[i];
        __nv_bfloat16 h = __float2bfloat16(v);
        hi[i] = h;
        lo[i] = __float2bfloat16(v - __bfloat162float(h));
    }
}
__global__ void splitT_kernel(const float* __restrict__ W,
                              __nv_bfloat16* __restrict__ hT,
                              __nv_bfloat16* __restrict__ lT, int K, int N) {
    __shared__ float t[32][33];
    int n0 = blockIdx.x * 32, k0 = blockIdx.y * 32;
    int tx = threadIdx.x, ty = threadIdx.y;
    #pragma unroll
    for (int i = 0; i < 32; i += 8)
        t[ty + i][tx] = W[(size_t)(k0 + ty + i) * N + n0 + tx];
    __syncthreads();
    #pragma unroll
    for (int i = 0; i < 32; i += 8) {
        float v = t[tx][ty + i];
        __nv_bfloat16 h = __float2bfloat16(v);
        size_t o = (size_t)(n0 + ty + i) * K + k0 + tx;
        hT[o] = h;
        lT[o] = __float2bfloat16(v - __bfloat162float(h));
    }
}

// ---------------------------------------------------------------------------
// Tensor-core GEMM (bf16x3 emulated fp32): C = A@W^T + bias.
// 128x128x32 block, 8 warps (64x32 warp tile), double-buffered cp.async.
// Epilogue: fp32 out (Cf) OR bf16 hi/lo split out (Ch/Cl).
// ---------------------------------------------------------------------------
#define LDK 40
#define MAT_ELEMS (128 * LDK)
#define STG_ELEMS (4 * MAT_ELEMS)
#define KTILES (Nq / 32)

__global__ __launch_bounds__(256, 2)
void gemm_mma(const __nv_bfloat16* __restrict__ Ah, const __nv_bfloat16* __restrict__ Al,
              const __nv_bfloat16* __restrict__ Bh, const __nv_bfloat16* __restrict__ Bl,
              const float* __restrict__ bias,
              float* __restrict__ Cf,
              __nv_bfloat16* __restrict__ Ch, __nv_bfloat16* __restrict__ Cl,
              int N) {
    extern __shared__ __nv_bfloat16 sm[];
    const int tid = threadIdx.x;
    const int lane = tid & 31, wid = tid >> 5;
    const int wm = wid & 1, wn = wid >> 1;
    const int bm0 = blockIdx.y * 128, bn0 = blockIdx.x * 128;
    const uint32_t sbase = smem_u32(sm);

    const __nv_bfloat16* srcs[4] = {
        Ah + (size_t)bm0 * Nq, Al + (size_t)bm0 * Nq,
        Bh + (size_t)bn0 * Nq, Bl + (size_t)bn0 * Nq };

    const int r_a = tid >> 2;
    const int c_a = tid & 3;

    float acc[4][4][4];
    #pragma unroll
    for (int i = 0; i < 4; i++)
        #pragma unroll
        for (int j = 0; j < 4; j++)
            #pragma unroll
            for (int k = 0; k < 4; k++) acc[i][j][k] = 0.0f;

    auto issue = [&](int buf, int kt) {
        uint32_t sb = sbase + (uint32_t)(buf * STG_ELEMS) * 2;
        #pragma unroll
        for (int mi = 0; mi < 4; mi++) {
            #pragma unroll
            for (int it = 0; it < 2; it++) {
                int r = r_a + it * 64;
                uint32_t sa = sb + (uint32_t)(mi * MAT_ELEMS + r * LDK + c_a * 8) * 2;
                cp16(sa, srcs[mi] + (size_t)r * Nq + kt * 32 + c_a * 8);
            }
        }
        cp_commit();
    };

    issue(0, 0);
    int buf = 0;

    const int aRow = wm * 64 + (lane & 15);
    const int aColL = (lane >> 4) * 8;
    const int bRow = wn * 32 + (lane & 7) + ((lane >> 4) << 3);
    const int bColL = ((lane >> 3) & 1) * 8;

    for (int kt = 0; kt < KTILES; kt++) {
        if (kt + 1 < KTILES) { issue(buf ^ 1, kt + 1); cp_wait<1>(); }
        else                 { cp_wait<0>(); }
        __syncthreads();

        uint32_t stg = sbase + (uint32_t)(buf * STG_ELEMS) * 2;
        uint32_t AHb = stg;
        uint32_t ALb = stg + (uint32_t)MAT_ELEMS * 2;
        uint32_t BHb = stg + (uint32_t)(2 * MAT_ELEMS) * 2;
        uint32_t BLb = stg + (uint32_t)(3 * MAT_ELEMS) * 2;

        #pragma unroll
        for (int ks = 0; ks < 2; ks++) {
            int kc = ks * 16;
            uint32_t ah[4][4], al[4][4], bh[2][4], bl[2][4];
            #pragma unroll
            for (int mt = 0; mt < 4; mt++)
                ldm4(ah[mt], AHb + (uint32_t)((aRow + mt * 16) * LDK + kc + aColL) * 2);
            #pragma unroll
            for (int p = 0; p < 2; p++)
                ldm4(bh[p], BHb + (uint32_t)((bRow + p * 16) * LDK + kc + bColL) * 2);
            #pragma unroll
            for (int mt = 0; mt < 4; mt++)
                #pragma unroll
                for (int nt = 0; nt < 4; nt++)
                    mma16816(acc[mt][nt], ah[mt], bh[nt >> 1][(nt & 1) * 2],
                             bh[nt >> 1][(nt & 1) * 2 + 1]);
            #pragma unroll
            for (int mt = 0; mt < 4; mt++)
                ldm4(al[mt], ALb + (uint32_t)((aRow + mt * 16) * LDK + kc + aColL) * 2);
            #pragma unroll
            for (int mt = 0; mt < 4; mt++)
                #pragma unroll
                for (int nt = 0; nt < 4; nt++)
                    mma16816(acc[mt][nt], al[mt], bh[nt >> 1][(nt & 1) * 2],
                             bh[nt >> 1][(nt & 1) * 2 + 1]);
            #pragma unroll
            for (int p = 0; p < 2; p++)
                ldm4(bl[p], BLb + (uint32_t)((bRow + p * 16) * LDK + kc + bColL) * 2);
            #pragma unroll
            for (int mt = 0; mt < 4; mt++)
                #pragma unroll
                for (int nt = 0; nt < 4; nt++)
                    mma16816(acc[mt][nt], ah[mt], bl[nt >> 1][(nt & 1) * 2],
                             bl[nt >> 1][(nt & 1) * 2 + 1]);
        }
        __syncthreads();
        buf ^= 1;
    }

    const int lr = lane >> 2, lc = lane & 3;
    #pragma unroll
    for (int mt = 0; mt < 4; mt++) {
        int row0 = bm0 + wm * 64 + mt * 16 + lr;
        #pragma unroll
        for (int nt = 0; nt < 4; nt++) {
            int col = bn0 + wn * 32 + nt * 8 + lc * 2;
            float2 bi = *(const float2*)&bias[col];
            float v00 = acc[mt][nt][0] + bi.x, v01 = acc[mt][nt][1] + bi.y;
            float v10 = acc[mt][nt][2] + bi.x, v11 = acc[mt][nt][3] + bi.y;
            if (Cf) {
                float2 o0 = {v00, v01}, o1 = {v10, v11};
                *(float2*)&Cf[(size_t)row0 * N + col] = o0;
                *(float2*)&Cf[(size_t)(row0 + 8) * N + col] = o1;
            } else {
                uint32_t h0 = cvt2(v01, v00);
                uint32_t h1 = cvt2(v11, v10);
                float r00 = v00 - __int_as_float(h0 << 16);
                float r01 = v01 - __int_as_float(h0 & 0xffff0000u);
                float r10 = v10 - __int_as_float(h1 << 16);
                float r11 = v11 - __int_as_float(h1 & 0xffff0000u);
                *(uint32_t*)&Ch[(size_t)row0 * N + col] = h0;
                *(uint32_t*)&Ch[(size_t)(row0 + 8) * N + col] = h1;
                *(uint32_t*)&Cl[(size_t)row0 * N + col] = cvt2(r01, r00);
                *(uint32_t*)&Cl[(size_t)(row0 + 8) * N + col] = cvt2(r11, r10);
            }
        }
    }
}

// ---------------------------------------------------------------------------
// Tensor-core causal flash attention (FA2-style, bf16 hi/lo splits).
// CTA: 128 q-rows x d=64, 8 warps x 16 rows. 64-key tiles, double buffered.
// ---------------------------------------------------------------------------
#define AQ 128
#define AKT 64
#define LDA 72
#define Q_ELEMS (2 * 128 * LDA)          // Qh + Ql
#define KV_STG  (4 * 64 * LDA)           // Kh,Kl,Vh,Vl per stage
#define ATT_SMEM ((Q_ELEMS + 2 * KV_STG) * 2)  // bytes = 110592

__global__ __launch_bounds__(256)
void attn_mma() {
    extern __shared__ __nv_bfloat16 sm[];
    const int tid = threadIdx.x, lane = tid & 31, wid = tid >> 5;
    const int bh = blockIdx.y, b = bh >> 4, h = bh & 15;
    const int qt = gridDim.x - 1 - blockIdx.x;   // heavy tiles first
    const int q0 = qt * AQ;
    const uint32_t sbase = smem_u32(sm);
    const size_t rowb = (size_t)b * Mq;

    // smem element offsets
    const uint32_t oQh = 0, oQl = 128 * LDA, oKV = Q_ELEMS;

    // ---- load Q tile (hi/lo) ----
    #pragma unroll
    for (int l = tid; l < 2048; l += 256) {
        int arr = l >> 10;               // 0:h 1:l
        int r = (l >> 3) & 127;
        int c = l & 7;
        const __nv_bfloat16* g = (arr ? g_qkvl : g_qkvh) +
            (rowb + q0 + r) * N3 + h * 64 + c * 8;
        cp16(sbase + ((arr ? oQl : oQh) + r * LDA + c * 8) * 2, g);
    }
    cp_commit();

    auto load_kv = [&](int stg, int j0) {
        uint32_t base = oKV + stg * KV_STG;
        #pragma unroll
        for (int l = tid; l < 2048; l += 256) {
            int arr = l >> 9;            // 0:Kh 1:Kl 2:Vh 3:Vl
            int r = (l >> 3) & 63;
            int c = l & 7;
            size_t roff = (rowb + j0 + r) * N3 + h * 64 + c * 8;
            const __nv_bfloat16* g =
                (arr == 0) ? g_qkvh + roff + Nq :
                (arr == 1) ? g_qkvl + roff + Nq :
                (arr == 2) ? g_qkvh + roff + 2 * Nq :
                             g_qkvl + roff + 2 * Nq;
            cp16(sbase + (base + arr * 64 * LDA + r * LDA + c * 8) * 2, g);
        }
        cp_commit();
    };

    load_kv(0, 0);

    // ---- Q fragments into registers (once) ----
    cp_wait<1>();          // Q group done (stage0 may still be pending)
    __syncthreads();
    uint32_t qhf[4][4], qlf[4][4];
    {
        int aRow = wid * 16 + (lane & 15);
        int aCol = (lane >> 4) * 8;
        #pragma unroll
        for (int ks = 0; ks < 4; ks++) {
            ldm4(qhf[ks], sbase + (oQh + aRow * LDA + ks * 16 + aCol) * 2);
            ldm4(qlf[ks], sbase + (oQl + aRow * LDA + ks * 16 + aCol) * 2);
        }
    }

    float m0 = -1e30f, m1 = -1e30f, l0 = 0.0f, l1 = 0.0f;
    float O[8][4];
    #pragma unroll
    for (int f = 0; f < 8; f++)
        #pragma unroll
        for (int c = 0; c < 4; c++) O[f][c] = 0.0f;

    const int nkt = (q0 + AQ) / AKT;
    int buf = 0;
    const float scale = 0.125f;
    const int rbase0 = q0 + wid * 16 + (lane >> 2);

    for (int kt = 0; kt < nkt; kt++) {
        const int j0 = kt * AKT;
        if (kt + 1 < nkt) { load_kv(buf ^ 1, j0 + AKT); cp_wait<1>(); }
        else              { cp_wait<0>(); }
        __syncthreads();

        const uint32_t stg = oKV + buf * KV_STG;
        const uint32_t sKh = sbase + stg * 2;
        const uint32_t sKl = sKh + (uint32_t)(64 * LDA) * 2;
        const uint32_t sVh = sKl + (uint32_t)(64 * LDA) * 2;
        const uint32_t sVl = sVh + (uint32_t)(64 * LDA) * 2;

        // ---- scores = Q K^T (3 split products) ----
        float s[8][4];
        #pragma unroll
        for (int f = 0; f < 8; f++)
            #pragma unroll
            for (int c = 0; c < 4; c++) s[f][c] = 0.0f;

        const int kRow = (lane & 7) + ((lane >> 4) << 3);
        const int kCol = ((lane >> 3) & 1) * 8;
        #pragma unroll
        for (int ks = 0; ks < 4; ks++) {
            #pragma unroll
            for (int p = 0; p < 4; p++) {
                uint32_t addr = sKh + (uint32_t)((p * 16 + kRow) * LDA + ks * 16 + kCol) * 2;
                uint32_t kh4[4], kl4[4];
                ldm4(kh4, addr);
                ldm4(kl4, addr + (uint32_t)(64 * LDA) * 2);  // Kl same offset
                mma16816(s[2 * p],     qhf[ks], kh4[0], kh4[1]);
                mma16816(s[2 * p + 1], qhf[ks], kh4[2], kh4[3]);
                mma16816(s[2 * p],     qhf[ks], kl4[0], kl4[1]);
                mma16816(s[2 * p + 1], qhf[ks], kl4[2], kl4[3]);
                mma16816(s[2 * p],     qlf[ks], kh4[0], kh4[1]);
                mma16816(s[2 * p + 1], qlf[ks], kh4[2], kh4[3]);
            }
        }

        // ---- scale + causal mask (diagonal tiles only) ----
        if (j0 + AKT - 1 > q0) {
            #pragma unroll
            for (int f = 0; f < 8; f++) {
                int k0c = j0 + f * 8 + (lane & 3) * 2;
                #pragma unroll
                for (int c = 0; c < 4; c++) {
                    int key = k0c + (c & 1);
                    int row = rbase0 + ((c >> 1) * 8);
                    s[f][c] = (key > row) ? -1e30f : s[f][c] * scale;
                }
            }
        } else {
            #pragma unroll
            for (int f = 0; f < 8; f++)
                #pragma unroll
                for (int c = 0; c < 4; c++) s[f][c] *= scale;
        }

        // ---- online softmax ----
        float bm0 = -1e30f, bm1 = -1e30f;
        #pragma unroll
        for (int f = 0; f < 8; f++) {
            bm0 = fmaxf(bm0, fmaxf(s[f][0], s[f][1]));
            bm1 = fmaxf(bm1, fmaxf(s[f][2], s[f][3]));
        }
        bm0 = fmaxf(bm0, __shfl_xor_sync(0xffffffff, bm0, 1));
        bm0 = fmaxf(bm0, __shfl_xor_sync(0xffffffff, bm0, 2));
        bm1 = fmaxf(bm1, __shfl_xor_sync(0xffffffff, bm1, 1));
        bm1 = fmaxf(bm1, __shfl_xor_sync(0xffffffff, bm1, 2));
        float mn0 = fmaxf(m0, bm0), mn1 = fmaxf(m1, bm1);
        float corr0 = fexp(m0 - mn0), corr1 = fexp(m1 - mn1);
        m0 = mn0; m1 = mn1;

        float es0 = 0.0f, es1 = 0.0f;
        #pragma unroll
        for (int f = 0; f < 8; f++) {
            s[f][0] = fexp(s[f][0] - m0);
            s[f][1] = fexp(s[f][1] - m0);
            s[f][2] = fexp(s[f][2] - m1);
            s[f][3] = fexp(s[f][3] - m1);
            es0 += s[f][0] + s[f][1];
            es1 += s[f][2] + s[f][3];
        }
        es0 += __shfl_xor_sync(0xffffffff, es0, 1);
        es0 += __shfl_xor_sync(0xffffffff, es0, 2);
        es1 += __shfl_xor_sync(0xffffffff, es1, 1);
        es1 += __shfl_xor_sync(0xffffffff, es1, 2);
        l0 = l0 * corr0 + es0;
        l1 = l1 * corr1 + es1;

        #pragma unroll
        for (int f = 0; f < 8; f++) {
            O[f][0] *= corr0; O[f][1] *= corr0;
            O[f][2] *= corr1; O[f][3] *= corr1;
        }

        // ---- P @ V (3 split products) ----
        const int vRow = lane & 15;
        const int vCol = (lane >> 4) * 8;
        #pragma unroll
        for (int ks2 = 0; ks2 < 4; ks2++) {
            uint32_t ahf[4], alf[4];
            #pragma unroll
            for (int q = 0; q < 2; q++) {       // two C-frags -> a0/a1 and a2/a3
                float p0 = s[2 * ks2 + q][0], p1 = s[2 * ks2 + q][1];
                float p2 = s[2 * ks2 + q][2], p3 = s[2 * ks2 + q][3];
                uint32_t h01 = cvt2(p1, p0);
                uint32_t h23 = cvt2(p3, p2);
                ahf[2 * q + 0] = h01;
                ahf[2 * q + 1] = h23;
                float r0 = p0 - __int_as_float(h01 << 16);
                float r1 = p1 - __int_as_float(h01 & 0xffff0000u);
                float r2 = p2 - __int_as_float(h23 << 16);
                float r3 = p3 - __int_as_float(h23 & 0xffff0000u);
                alf[2 * q + 0] = cvt2(r1, r0);
                alf[2 * q + 1] = cvt2(r3, r2);
            }
            // NOTE: a-frag order must be {a0,a1,a2,a3} = {h of frag0 rows, frag0 rows+8,
            // frag1 rows, frag1 rows+8} -> reorder:
            uint32_t aH[4] = {ahf[0], ahf[1], ahf[2], ahf[3]};
            uint32_t aL[4] = {alf[0], alf[1], alf[2], alf[3]};
            #pragma unroll
            for (int p2i = 0; p2i < 4; p2i++) {
                uint32_t addr = sVh + (uint32_t)((vRow + ks2 * 16) * LDA + p2i * 16 + vCol) * 2;
                uint32_t vh4[4], vl4[4];
                ldm4t(vh4, addr);
                ldm4t(vl4, addr + (sVl - sVh));
                mma16816(O[2 * p2i],     aH, vh4[0], vh4[1]);
                mma16816(O[2 * p2i + 1], aH, vh4[2], vh4[3]);
                mma16816(O[2 * p2i],     aH, vl4[0], vl4[1]);
                mma16816(O[2 * p2i + 1], aH, vl4[2], vl4[3]);
                mma16816(O[2 * p2i],     aL, vh4[0], vh4[1]);
                mma16816(O[2 * p2i + 1], aL, vh4[2], vh4[3]);
            }
        }
        __syncthreads();
        buf ^= 1;
    }

    // ---- epilogue: normalize, write ctx bf16 hi/lo ----
    float inv0 = 1.0f / l0, inv1 = 1.0f / l1;
    int gr0 = rbase0;
    size_t base0 = (rowb + gr0) * Nq + h * 64;
    size_t base1 = (rowb + gr0 + 8) * Nq + h * 64;
    #pragma unroll
    for (int f = 0; f < 8; f++) {
        int col = f * 8 + (lane & 3) * 2;
        float v00 = O[f][0] * inv0, v01 = O[f][1] * inv0;
        float v10 = O[f][2] * inv1, v11 = O[f][3] * inv1;
        uint32_t h0 = cvt2(v01, v00);
        uint32_t h1 = cvt2(v11, v10);
        float r00 = v00 - __int_as_float(h0 << 16);
        float r01 = v01 - __int_as_float(h0 & 0xffff0000u);
        float r10 = v10 - __int_as_float(h1 << 16);
        float r11 = v11 - __int_as_float(h1 & 0xffff0000u);
        *(uint32_t*)&g_ch[base0 + col] = h0;
        *(uint32_t*)&g_cl[base0 + col] = cvt2(r01, r00);
        *(uint32_t*)&g_ch[base1 + col] = h1;
        *(uint32_t*)&g_cl[base1 + col] = cvt2(r11, r10);
    }
}

// ---------------------------------------------------------------------------
extern "C" void kernel_launch(void* const* d_in, const int* in_sizes, int n_in,
                              void* d_out, int out_size) {
    const float* x      = (const float*)d_in[0];
    const float* w_attn = (const float*)d_in[1];
    const float* w_proj = (const float*)d_in[2];
    const float* b_attn = (const float*)d_in[3];
    const float* b_proj = (const float*)d_in[4];
    float* out = (float*)d_out;

    __nv_bfloat16 *qh, *ql, *xh, *xl, *wah, *wal, *wph, *wpl, *ch, *cl;
    cudaGetSymbolAddress((void**)&qh, g_qkvh);
    cudaGetSymbolAddress((void**)&ql, g_qkvl);
    cudaGetSymbolAddress((void**)&xh, g_xh);
    cudaGetSymbolAddress((void**)&xl, g_xl);
    cudaGetSymbolAddress((void**)&wah, g_wah);
    cudaGetSymbolAddress((void**)&wal, g_wal);
    cudaGetSymbolAddress((void**)&wph, g_wph);
    cudaGetSymbolAddress((void**)&wpl, g_wpl);
    cudaGetSymbolAddress((void**)&ch, g_ch);
    cudaGetSymbolAddress((void**)&cl, g_cl);

    static bool attr_set = false;
    if (!attr_set) {
        cudaFuncSetAttribute(gemm_mma, cudaFuncAttributeMaxDynamicSharedMemorySize,
                             2 * STG_ELEMS * 2);
        cudaFuncSetAttribute(attn_mma, cudaFuncAttributeMaxDynamicSharedMemorySize,
                             ATT_SMEM);
        attr_set = true;
    }

    // conversions
    {
        int n = MB * Nq;
        split_kernel<<<(n + 255) / 256, 256>>>(x, xh, xl, n);
    }
    splitT_kernel<<<dim3(N3 / 32, Nq / 32), dim3(32, 8)>>>(w_attn, wah, wal, Nq, N3);
    splitT_kernel<<<dim3(Nq / 32, Nq / 32), dim3(32, 8)>>>(w_proj, wph, wpl, Nq, Nq);

    // QKV projection -> bf16 hi/lo qkv
    gemm_mma<<<dim3(N3 / 128, MB / 128), 256, 2 * STG_ELEMS * 2>>>(
        xh, xl, wah, wal, b_attn, nullptr, qh, ql, N3);

    // causal flash attention -> ctx hi/lo
    attn_mma<<<dim3(Mq / AQ, Bq * Hh), 256, ATT_SMEM>>>();

    // output projection -> fp32 out
    gemm_mma<<<dim3(Nq / 128, MB / 128), 256, 2 * STG_ELEMS * 2>>>(
        ch, cl, wph, wpl, b_proj, out, nullptr, nullptr, Nq);
}